// round 3
// baseline (speedup 1.0000x reference)
#include <cuda_runtime.h>
#include <math.h>
#include <stddef.h>

// Problem constants
#define T_LEN 256
#define B_SZ  256
#define H_DIM 512
#define R_ROWS 768          // 3 texts * 256 batch
#define G_COLS 2048         // 4*H
#define M_ALL  196608       // T_LEN * R_ROWS
#define H5 102              // H/5

// ---------------- static device scratch (no allocations allowed) ------------
__device__ float d_Xbuf[100663296];   // [T][768][512] layer input
__device__ float d_Ybuf[100663296];   // [T][768][512] layer output
__device__ float d_Gbuf[402653184];   // [T][768][2048] precomputed x@Wx + b
__device__ float d_cst[393216];       // [768][512] cell state
__device__ float d_rbuf[393216];      // [256][1536]
__device__ float d_h1buf[262144];     // [256][1024]
__device__ float d_h2buf[26112];      // [256][102]

// ---------------- embedding gather ------------------------------------------
__global__ void clstm_embed(const int* __restrict__ t1, const int* __restrict__ t2,
                            const int* __restrict__ t3, const float* __restrict__ emb,
                            float* __restrict__ X) {
    int row = blockIdx.x;            // 0..767
    int t   = blockIdx.y;            // 0..255
    int text = row >> 8, b = row & 255;
    const int* tp = (text == 0) ? t1 : (text == 1 ? t2 : t3);
    int tok = tp[b * T_LEN + t];
    const float4* src = (const float4*)(emb + (size_t)tok * H_DIM);
    float4* dst = (float4*)(X + ((size_t)t * R_ROWS + row) * H_DIM);
    dst[threadIdx.x] = src[threadIdx.x];   // 128 threads * float4 = 512 floats
}

// ---------------- big fp32 GEMM: C[M,N] = A[M,K]*Bm[K,N] + bias[N] ----------
// 128x128 block tile, K-step 16, 256 threads, 8x8 per thread. (near roofline)
__global__ void __launch_bounds__(256)
clstm_gemm_bias(const float* __restrict__ A, const float* __restrict__ Bm,
                const float* __restrict__ bias, float* __restrict__ C,
                int M, int N, int K) {
    __shared__ float As[16][132];
    __shared__ float Bs[16][128];
    int bn = blockIdx.x * 128;
    int bm = blockIdx.y * 128;
    int tid = threadIdx.x;
    int tx = tid & 15, ty = tid >> 4;
    float acc[8][8];
#pragma unroll
    for (int i = 0; i < 8; i++)
#pragma unroll
        for (int j = 0; j < 8; j++) acc[i][j] = 0.f;

    for (int k0 = 0; k0 < K; k0 += 16) {
#pragma unroll
        for (int i = 0; i < 2; i++) {
            int idx = tid + i * 256;           // 0..511
            int r = idx >> 2, c4 = (idx & 3) << 2;
            float4 v = *(const float4*)(A + (size_t)(bm + r) * K + k0 + c4);
            As[c4 + 0][r] = v.x; As[c4 + 1][r] = v.y;
            As[c4 + 2][r] = v.z; As[c4 + 3][r] = v.w;
        }
#pragma unroll
        for (int i = 0; i < 2; i++) {
            int idx = tid + i * 256;
            int kr = idx >> 5, nc = (idx & 31) << 2;
            *(float4*)(&Bs[kr][nc]) =
                *(const float4*)(Bm + (size_t)(k0 + kr) * N + bn + nc);
        }
        __syncthreads();
#pragma unroll
        for (int kk = 0; kk < 16; kk++) {
            float a[8], bb[8];
#pragma unroll
            for (int i = 0; i < 8; i++) a[i] = As[kk][ty * 8 + i];
#pragma unroll
            for (int j = 0; j < 8; j++) bb[j] = Bs[kk][tx * 8 + j];
#pragma unroll
            for (int i = 0; i < 8; i++)
#pragma unroll
                for (int j = 0; j < 8; j++) acc[i][j] += a[i] * bb[j];
        }
        __syncthreads();
    }
#pragma unroll
    for (int i = 0; i < 8; i++) {
        size_t rowoff = (size_t)(bm + ty * 8 + i) * N + bn;
#pragma unroll
        for (int j = 0; j < 8; j++)
            C[rowoff + tx * 8 + j] = acc[i][j] + bias[bn + tx * 8 + j];
    }
}

// ---------------- fused recurrent step (v2: 32x32 tiles, 384 CTAs) ----------
// grid (16, 24): blockIdx.x = 32-hcol block (4 gate strips of 32 cols),
// blockIdx.y = 32-row block of the 768 batch rows.
// Per CTA: gates[32,128] = hprev[32,512] @ Wh[:,strips] + Gt, then LSTM update.
// 256 threads: lane = tid&31 owns 4 gate-cols (lane*4), wy = tid>>5 owns 4 rows.
// Inner loop: 2x LDS.128 + 16 FFMA per kk. Smem (16KB) unioned: As/Bs then gsm.
__global__ void __launch_bounds__(256)
clstm_step(const float* __restrict__ Gt, const float* __restrict__ hprev,
           const float* __restrict__ Wh, float* __restrict__ cst,
           float* __restrict__ hout, int t0) {
    __shared__ float sm[4096];       // max(32*128 gsm, 576 As + 2048 Bs)
    float* As = sm;                  // [16][36]  (k-major, padded)
    float* Bs = sm + 576;            // [16][128]
    int cb = blockIdx.x;             // h-col block (32 cols)
    int bm = blockIdx.y * 32;        // row base
    int tid = threadIdx.x;
    int lane = tid & 31, wy = tid >> 5;

    float acc[4][4];
#pragma unroll
    for (int i = 0; i < 4; i++)
#pragma unroll
        for (int j = 0; j < 4; j++) acc[i][j] = 0.f;

    if (!t0) {
        for (int k0 = 0; k0 < H_DIM; k0 += 16) {
            // As: 32 rows x 16 k -> transposed, 128 float4 loads (tid<128)
            if (tid < 128) {
                int r = tid >> 2, c4 = (tid & 3) << 2;
                float4 v = *(const float4*)(hprev + (size_t)(bm + r) * H_DIM + k0 + c4);
                As[(c4 + 0) * 36 + r] = v.x;
                As[(c4 + 1) * 36 + r] = v.y;
                As[(c4 + 2) * 36 + r] = v.z;
                As[(c4 + 3) * 36 + r] = v.w;
            }
            // Bs: 16 k x 128 gate-cols, 512 float4 loads
#pragma unroll
            for (int i = 0; i < 2; i++) {
                int idx = tid + i * 256;            // 0..511
                int kr = idx >> 5, lc = (idx & 31) << 2;
                int gate = lc >> 5, w = lc & 31;
                *(float4*)(Bs + kr * 128 + lc) =
                    *(const float4*)(Wh + (size_t)(k0 + kr) * G_COLS +
                                     gate * H_DIM + cb * 32 + w);
            }
            __syncthreads();
#pragma unroll
            for (int kk = 0; kk < 16; kk++) {
                float4 a = *(const float4*)(As + kk * 36 + wy * 4);   // broadcast
                float4 b = *(const float4*)(Bs + kk * 128 + lane * 4);
                acc[0][0] += a.x * b.x; acc[0][1] += a.x * b.y;
                acc[0][2] += a.x * b.z; acc[0][3] += a.x * b.w;
                acc[1][0] += a.y * b.x; acc[1][1] += a.y * b.y;
                acc[1][2] += a.y * b.z; acc[1][3] += a.y * b.w;
                acc[2][0] += a.z * b.x; acc[2][1] += a.z * b.y;
                acc[2][2] += a.z * b.z; acc[2][3] += a.z * b.w;
                acc[3][0] += a.w * b.x; acc[3][1] += a.w * b.y;
                acc[3][2] += a.w * b.z; acc[3][3] += a.w * b.w;
            }
            __syncthreads();
        }
    }
    // stash gate partials into gsm (reuses As/Bs space)
    float* gsm = sm;                 // [32][128]
#pragma unroll
    for (int i = 0; i < 4; i++)
        *(float4*)(gsm + (wy * 4 + i) * 128 + lane * 4) =
            make_float4(acc[i][0], acc[i][1], acc[i][2], acc[i][3]);
    __syncthreads();

    // epilogue: 32 rows x 32 h-cols = 1024 elements, 4 per thread
#pragma unroll
    for (int q = 0; q < 4; q++) {
        int e = tid + q * 256;
        int r = e >> 5, j = e & 31;
        int grow = bm + r;
        int hc = cb * 32 + j;
        size_t gbase = (size_t)grow * G_COLS;
        float xi = gsm[r * 128 +       j] + Gt[gbase +             hc];
        float xf = gsm[r * 128 +  32 + j] + Gt[gbase +   H_DIM  + hc];
        float xg = gsm[r * 128 +  64 + j] + Gt[gbase + 2*H_DIM  + hc];
        float xo = gsm[r * 128 +  96 + j] + Gt[gbase + 3*H_DIM  + hc];
        float ig = 1.f / (1.f + expf(-xi));
        float fg = 1.f / (1.f + expf(-xf));
        float gg = tanhf(xg);
        float og = 1.f / (1.f + expf(-xo));
        size_t cidx = (size_t)grow * H_DIM + hc;
        float cn = fg * cst[cidx] + ig * gg;
        cst[cidx] = cn;
        hout[cidx] = og * tanhf(cn);
    }
}

// ---------------- head kernels ----------------------------------------------
__global__ void clstm_gather_r(const float* __restrict__ Ytop, float* __restrict__ r) {
    int b = blockIdx.x, i = blockIdx.y, h = threadIdx.x;   // block 512
    r[(size_t)b * 1536 + i * H_DIM + h] =
        Ytop[((size_t)(T_LEN - 1) * R_ROWS + i * B_SZ + b) * H_DIM + h];
}

// batchnorm over batch dim (M=256 rows == blockDim), one block per column
__global__ void clstm_bn(float* __restrict__ x, const float* __restrict__ gamma,
                         const float* __restrict__ beta, int N) {
    __shared__ float s1[256], s2[256];
    int col = blockIdx.x;
    float v = x[(size_t)threadIdx.x * N + col];
    s1[threadIdx.x] = v;
    s2[threadIdx.x] = v * v;
    __syncthreads();
    for (int s = 128; s > 0; s >>= 1) {
        if (threadIdx.x < s) {
            s1[threadIdx.x] += s1[threadIdx.x + s];
            s2[threadIdx.x] += s2[threadIdx.x + s];
        }
        __syncthreads();
    }
    float m = s1[0] * (1.f / 256.f);
    float var = s2[0] * (1.f / 256.f) - m * m;
    float inv = rsqrtf(var + 1e-3f);
    x[(size_t)threadIdx.x * N + col] = gamma[col] * (v - m) * inv + beta[col];
}

// small head GEMM: C[M,N] = act(A[M,K] @ W[K,N] + bias), 16 rows per block
__global__ void clstm_gemm_head(const float* __restrict__ A, const float* __restrict__ W,
                                const float* __restrict__ bias, float* __restrict__ C,
                                int K, int N, int act) {
    int n = blockIdx.x * 128 + threadIdx.x;
    int m0 = blockIdx.y * 16;
    if (n >= N) return;
    float s[16];
#pragma unroll
    for (int mm = 0; mm < 16; mm++) s[mm] = bias[n];
    for (int k = 0; k < K; k++) {
        float w = W[(size_t)k * N + n];
#pragma unroll
        for (int mm = 0; mm < 16; mm++)
            s[mm] += A[(size_t)(m0 + mm) * K + k] * w;
    }
    const float alpha = 1.6732632423543772f, scale = 1.0507009873554805f;
#pragma unroll
    for (int mm = 0; mm < 16; mm++) {
        float v = s[mm];
        if (act) v = scale * (v > 0.f ? v : alpha * expm1f(v));
        C[(size_t)(m0 + mm) * N + n] = v;
    }
}

// ---------------- launch ------------------------------------------------------
extern "C" void kernel_launch(void* const* d_in, const int* in_sizes, int n_in,
                              void* d_out, int out_size) {
    const int*   t1   = (const int*)d_in[0];
    const int*   t2   = (const int*)d_in[1];
    const int*   t3   = (const int*)d_in[2];
    const float* emb  = (const float*)d_in[3];
    const float* Wx   = (const float*)d_in[4];
    const float* Wh   = (const float*)d_in[5];
    const float* bb   = (const float*)d_in[6];
    const float* g1   = (const float*)d_in[7];
    const float* be1  = (const float*)d_in[8];
    const float* W1   = (const float*)d_in[9];
    const float* bd1  = (const float*)d_in[10];
    const float* g2   = (const float*)d_in[11];
    const float* be2  = (const float*)d_in[12];
    const float* W2   = (const float*)d_in[13];
    const float* bd2  = (const float*)d_in[14];
    const float* g3   = (const float*)d_in[15];
    const float* be3  = (const float*)d_in[16];
    const float* W3   = (const float*)d_in[17];
    const float* bd3  = (const float*)d_in[18];
    float* out = (float*)d_out;

    float *X, *Y, *G, *C, *R, *H1, *H2;
    cudaGetSymbolAddress((void**)&X,  d_Xbuf);
    cudaGetSymbolAddress((void**)&Y,  d_Ybuf);
    cudaGetSymbolAddress((void**)&G,  d_Gbuf);
    cudaGetSymbolAddress((void**)&C,  d_cst);
    cudaGetSymbolAddress((void**)&R,  d_rbuf);
    cudaGetSymbolAddress((void**)&H1, d_h1buf);
    cudaGetSymbolAddress((void**)&H2, d_h2buf);

    // 1) embedding -> X  [T][768][512]
    clstm_embed<<<dim3(R_ROWS, T_LEN), 128>>>(t1, t2, t3, emb, X);

    float* inb = X;
    float* outb = Y;
    for (int l = 0; l < 3; l++) {
        // 2) G = inb @ Wx_l + b_l   (batched over all T and all 3 texts)
        clstm_gemm_bias<<<dim3(G_COLS / 128, M_ALL / 128), 256>>>(
            inb, Wx + (size_t)l * H_DIM * G_COLS, bb + (size_t)l * G_COLS, G,
            M_ALL, G_COLS, H_DIM);
        // 3) reset cell state
        cudaMemsetAsync(C, 0, (size_t)R_ROWS * H_DIM * sizeof(float), 0);
        // 4) 256 recurrent steps (fused GEMM + LSTM update)
        for (int t = 0; t < T_LEN; t++) {
            clstm_step<<<dim3(16, 24), 256>>>(
                G + (size_t)t * R_ROWS * G_COLS,
                outb + (size_t)(t > 0 ? t - 1 : 0) * R_ROWS * H_DIM,
                Wh + (size_t)l * H_DIM * G_COLS, C,
                outb + (size_t)t * R_ROWS * H_DIM, t == 0 ? 1 : 0);
        }
        float* tmp = inb; inb = outb; outb = tmp;   // next layer reads this output
    }
    // top-layer outputs are now in `inb`

    // 5) head: r = concat(last hidden of 3 texts) [256,1536]
    clstm_gather_r<<<dim3(B_SZ, 3), H_DIM>>>(inb, R);
    clstm_bn<<<1536, 256>>>(R, g1, be1, 1536);
    clstm_gemm_head<<<dim3(8, 16), 128>>>(R, W1, bd1, H1, 1536, 1024, 1);
    clstm_bn<<<1024, 256>>>(H1, g2, be2, 1024);
    clstm_gemm_head<<<dim3(1, 16), 128>>>(H1, W2, bd2, H2, 1024, H5, 1);
    clstm_bn<<<H5, 256>>>(H2, g3, be3, H5);
    clstm_gemm_head<<<dim3(1, 16), 128>>>(H2, W3, bd3, out, H5, 4, 0);
}

// round 5
// speedup vs baseline: 1.4921x; 1.4921x over previous
#include <cuda_runtime.h>
#include <cuda_bf16.h>
#include <math.h>
#include <stdint.h>
#include <stddef.h>

#define T_LEN 256
#define B_SZ  256
#define H_DIM 512
#define R_ROWS 768
#define G_COLS 2048
#define M_ALL  196608
#define H5 102

// ---------------- static device scratch --------------------------------------
__device__ float d_Xbuf[100663296];   // [T][768][512]
__device__ float d_Ybuf[100663296];   // [T][768][512]
__device__ float d_Gbuf[402653184];   // [T][768][2048]
__device__ float d_cst[393216];
__device__ float d_rbuf[393216];
__device__ float d_h1buf[262144];
__device__ float d_h2buf[26112];
__device__ __nv_bfloat16 d_WhPhi[3 * 2048 * 512];   // permuted [n'][k] hi
__device__ __nv_bfloat16 d_WhPlo[3 * 2048 * 512];   // permuted [n'][k] lo
__device__ __nv_bfloat16 d_hhi[2][393216];          // h hi, ping-pong
__device__ __nv_bfloat16 d_hlo[2][393216];          // h lo, ping-pong

// ---------------- helpers ------------------------------------------------------
__device__ __forceinline__ uint32_t smem_to_u32(const void* p) {
    uint32_t a;
    asm("{ .reg .u64 t; cvta.to.shared.u64 t, %1; cvt.u32.u64 %0, t; }"
        : "=r"(a) : "l"(p));
    return a;
}
__device__ __forceinline__ void ldmx4(uint32_t* r, uint32_t addr) {
    asm volatile("ldmatrix.sync.aligned.m8n8.x4.shared.b16 {%0,%1,%2,%3}, [%4];"
                 : "=r"(r[0]), "=r"(r[1]), "=r"(r[2]), "=r"(r[3]) : "r"(addr));
}
__device__ __forceinline__ void mma_bf16(float* c, const uint32_t* a,
                                         uint32_t b0, uint32_t b1) {
    asm volatile(
        "mma.sync.aligned.m16n8k16.row.col.f32.bf16.bf16.f32 "
        "{%0,%1,%2,%3}, {%4,%5,%6,%7}, {%8,%9}, {%0,%1,%2,%3};"
        : "+f"(c[0]), "+f"(c[1]), "+f"(c[2]), "+f"(c[3])
        : "r"(a[0]), "r"(a[1]), "r"(a[2]), "r"(a[3]), "r"(b0), "r"(b1));
}
#define CP_ASYNC16(dst, src) \
    asm volatile("cp.async.cg.shared.global [%0], [%1], 16;" :: "r"(dst), "l"(src))
#define CP_COMMIT()  asm volatile("cp.async.commit_group;" ::: "memory")
#define CP_WAIT0()   asm volatile("cp.async.wait_group 0;" ::: "memory")
#define CP_WAIT1()   asm volatile("cp.async.wait_group 1;" ::: "memory")

// ---------------- embedding gather --------------------------------------------
__global__ void clstm_embed(const int* __restrict__ t1, const int* __restrict__ t2,
                            const int* __restrict__ t3, const float* __restrict__ emb,
                            float* __restrict__ X) {
    int row = blockIdx.x, t = blockIdx.y;
    int text = row >> 8, b = row & 255;
    const int* tp = (text == 0) ? t1 : (text == 1 ? t2 : t3);
    int tok = tp[b * T_LEN + t];
    const float4* src = (const float4*)(emb + (size_t)tok * H_DIM);
    float4* dst = (float4*)(X + ((size_t)t * R_ROWS + row) * H_DIM);
    dst[threadIdx.x] = src[threadIdx.x];
}

// ---------------- Wh -> permuted transposed bf16 split -------------------------
// WhP[l][n'][k], n' = cb*128 + gate*32 + w for orig col n = gate*512 + cb*32 + w
__global__ void clstm_makeWhP(const float* __restrict__ Wh,
                              __nv_bfloat16* __restrict__ Phi,
                              __nv_bfloat16* __restrict__ Plo) {
    __shared__ float tile[32][33];
    int n0 = blockIdx.x * 32, k0 = blockIdx.y * 32, l = blockIdx.z;
    const float* W = Wh + (size_t)l * H_DIM * G_COLS;
    int tx = threadIdx.x, ty = threadIdx.y;
#pragma unroll
    for (int it = 0; it < 4; it++)
        tile[ty + it * 8][tx] = W[(size_t)(k0 + ty + it * 8) * G_COLS + n0 + tx];
    __syncthreads();
    int s = n0 >> 9, cbb = (n0 >> 5) & 15;
    int np0 = cbb * 128 + s * 32;
    __nv_bfloat16* ph = Phi + (size_t)l * G_COLS * H_DIM;
    __nv_bfloat16* pl = Plo + (size_t)l * G_COLS * H_DIM;
#pragma unroll
    for (int it = 0; it < 4; it++) {
        int nn = ty + it * 8;
        float v = tile[tx][nn];
        __nv_bfloat16 hi = __float2bfloat16(v);
        __nv_bfloat16 lo = __float2bfloat16(v - __bfloat162float(hi));
        ph[(size_t)(np0 + nn) * H_DIM + k0 + tx] = hi;
        pl[(size_t)(np0 + nn) * H_DIM + k0 + tx] = lo;
    }
}

// ---------------- big fp32 GEMM (gate precompute, ~roofline) -------------------
__global__ void __launch_bounds__(256)
clstm_gemm_bias(const float* __restrict__ A, const float* __restrict__ Bm,
                const float* __restrict__ bias, float* __restrict__ C,
                int M, int N, int K) {
    __shared__ float As[16][132];
    __shared__ float Bs[16][128];
    int bn = blockIdx.x * 128, bm = blockIdx.y * 128;
    int tid = threadIdx.x, tx = tid & 15, ty = tid >> 4;
    float acc[8][8];
#pragma unroll
    for (int i = 0; i < 8; i++)
#pragma unroll
        for (int j = 0; j < 8; j++) acc[i][j] = 0.f;
    for (int k0 = 0; k0 < K; k0 += 16) {
#pragma unroll
        for (int i = 0; i < 2; i++) {
            int idx = tid + i * 256, r = idx >> 2, c4 = (idx & 3) << 2;
            float4 v = *(const float4*)(A + (size_t)(bm + r) * K + k0 + c4);
            As[c4 + 0][r] = v.x; As[c4 + 1][r] = v.y;
            As[c4 + 2][r] = v.z; As[c4 + 3][r] = v.w;
        }
#pragma unroll
        for (int i = 0; i < 2; i++) {
            int idx = tid + i * 256, kr = idx >> 5, nc = (idx & 31) << 2;
            *(float4*)(&Bs[kr][nc]) = *(const float4*)(Bm + (size_t)(k0 + kr) * N + bn + nc);
        }
        __syncthreads();
#pragma unroll
        for (int kk = 0; kk < 16; kk++) {
            float a[8], bb[8];
#pragma unroll
            for (int i = 0; i < 8; i++) a[i] = As[kk][ty * 8 + i];
#pragma unroll
            for (int j = 0; j < 8; j++) bb[j] = Bs[kk][tx * 8 + j];
#pragma unroll
            for (int i = 0; i < 8; i++)
#pragma unroll
                for (int j = 0; j < 8; j++) acc[i][j] += a[i] * bb[j];
        }
        __syncthreads();
    }
#pragma unroll
    for (int i = 0; i < 8; i++) {
        size_t ro = (size_t)(bm + ty * 8 + i) * N + bn;
#pragma unroll
        for (int j = 0; j < 8; j++)
            C[ro + tx * 8 + j] = acc[i][j] + bias[bn + tx * 8 + j];
    }
}

// ---------------- HMMA (mma.sync) recurrent step -------------------------------
// grid (16,6), 256 thr (8 warps). CTA tile: 128 rows x 128 gate cols (permuted:
// 4 gate strips x 32 h-cols). gates = Ahi*Bhi + Ahi*Blo + Alo*Bhi (split bf16,
// fp32 accum) + Gt, then fused LSTM update.
// SMEM: 2 stages x 4 planes x [128 rows x 72 bf16 (144B, conflict-free)] = 144KB.
#define PLANE_B 18432           // 128*144
#define STAGE_B 73728           // 4 planes
#define STEP_SMEM 147456
__global__ void __launch_bounds__(256)
clstm_step_mma(const float* __restrict__ Gt,
               const __nv_bfloat16* __restrict__ Ahi, const __nv_bfloat16* __restrict__ Alo,
               const __nv_bfloat16* __restrict__ Bhi, const __nv_bfloat16* __restrict__ Blo,
               float* __restrict__ cst, float* __restrict__ hout,
               __nv_bfloat16* __restrict__ Hhi, __nv_bfloat16* __restrict__ Hlo) {
    extern __shared__ char smem[];
    const uint32_t sb = smem_to_u32(smem);
    const int tid = threadIdx.x;
    const int lane = tid & 31, w = tid >> 5;
    const int cb = blockIdx.x, bm = blockIdx.y * 128;

    const __nv_bfloat16* gsrc[4] = {
        Ahi + (size_t)bm * H_DIM, Alo + (size_t)bm * H_DIM,
        Bhi + (size_t)(cb * 128) * H_DIM, Blo + (size_t)(cb * 128) * H_DIM };

    // per-thread load slots: 4 chunks of 16B per plane per 64-K chunk
    const int lr = tid >> 3, lq = tid & 7;       // row group base, 16B chunk

    // issue one 64-wide K chunk into stage s
    auto load_chunk = [&](int c, int s) {
        uint32_t stg = sb + (uint32_t)s * STAGE_B;
#pragma unroll
        for (int p = 0; p < 4; p++) {
            const __nv_bfloat16* gb = gsrc[p] + c * 64;
            uint32_t sdst = stg + p * PLANE_B;
#pragma unroll
            for (int i = 0; i < 4; i++) {
                int r = lr + i * 32;
                uint32_t d = sdst + r * 144 + lq * 16;
                CP_ASYNC16(d, (const void*)(gb + (size_t)r * H_DIM + lq * 8));
            }
        }
        CP_COMMIT();
    };

    // warp tile: rows m0..m0+31, cols n0..n0+63
    const int m0 = (w >> 1) * 32, n0 = (w & 1) * 64;
    const int arow = (lane & 7) + ((lane & 8) ? 8 : 0);
    const int akq  = (lane & 16) ? 16 : 0;
    const int brow = (lane & 7) + ((lane & 16) ? 8 : 0);
    const int bkq  = (lane & 8) ? 16 : 0;

    float acc[2][8][4];
#pragma unroll
    for (int mt = 0; mt < 2; mt++)
#pragma unroll
        for (int nt = 0; nt < 8; nt++)
#pragma unroll
            for (int e = 0; e < 4; e++) acc[mt][nt][e] = 0.f;

    load_chunk(0, 0);
    for (int c = 0; c < 8; c++) {
        if (c < 7) { load_chunk(c + 1, (c + 1) & 1); CP_WAIT1(); }
        else       { CP_WAIT0(); }
        __syncthreads();
        uint32_t stg = sb + (uint32_t)(c & 1) * STAGE_B;
        uint32_t aH = stg, aL = stg + PLANE_B;
        uint32_t bH = stg + 2 * PLANE_B, bL = stg + 3 * PLANE_B;
#pragma unroll
        for (int ks = 0; ks < 4; ks++) {
            int kb = ks * 32;
            uint32_t ah[2][4], al[2][4], bh[4][4], bl[4][4];
#pragma unroll
            for (int mt = 0; mt < 2; mt++) {
                ldmx4(ah[mt], aH + (m0 + mt * 16 + arow) * 144 + kb + akq);
                ldmx4(al[mt], aL + (m0 + mt * 16 + arow) * 144 + kb + akq);
            }
#pragma unroll
            for (int p = 0; p < 4; p++) {
                ldmx4(bh[p], bH + (n0 + p * 16 + brow) * 144 + kb + bkq);
                ldmx4(bl[p], bL + (n0 + p * 16 + brow) * 144 + kb + bkq);
            }
#pragma unroll
            for (int mt = 0; mt < 2; mt++)
#pragma unroll
                for (int nt = 0; nt < 8; nt++) {
                    uint32_t h0 = bh[nt >> 1][(nt & 1) * 2], h1 = bh[nt >> 1][(nt & 1) * 2 + 1];
                    uint32_t l0 = bl[nt >> 1][(nt & 1) * 2], l1 = bl[nt >> 1][(nt & 1) * 2 + 1];
                    mma_bf16(acc[mt][nt], ah[mt], h0, h1);
                    mma_bf16(acc[mt][nt], ah[mt], l0, l1);
                    mma_bf16(acc[mt][nt], al[mt], h0, h1);
                }
        }
        __syncthreads();
    }

    // stage accumulators to smem gates tile [128][132]
    float* gsm = (float*)smem;
#pragma unroll
    for (int mt = 0; mt < 2; mt++)
#pragma unroll
        for (int nt = 0; nt < 8; nt++) {
            int row = m0 + mt * 16 + (lane >> 2);
            int col = n0 + nt * 8 + (lane & 3) * 2;
            gsm[row * 132 + col]     = acc[mt][nt][0];
            gsm[row * 132 + col + 1] = acc[mt][nt][1];
            gsm[(row + 8) * 132 + col]     = acc[mt][nt][2];
            gsm[(row + 8) * 132 + col + 1] = acc[mt][nt][3];
        }
    __syncthreads();

    // fused LSTM epilogue: thread -> row = tid>>1, 16 h-cols
    const int row = tid >> 1, hb = (tid & 1) * 16;
    const int grow = bm + row;
    const int hc0 = cb * 32 + hb;
    const float* gp = Gt + (size_t)grow * G_COLS + hc0;
    const float* cr = cst + (size_t)grow * H_DIM + hc0;
    float* hp = hout + (size_t)grow * H_DIM + hc0;
    float* cp = cst + (size_t)grow * H_DIM + hc0;
    __nv_bfloat16* hhp = Hhi + (size_t)grow * H_DIM + hc0;
    __nv_bfloat16* hlp = Hlo + (size_t)grow * H_DIM + hc0;
#pragma unroll
    for (int q = 0; q < 4; q++) {
        float4 gi = *(const float4*)(gp + q * 4);
        float4 gf = *(const float4*)(gp + 512 + q * 4);
        float4 gg = *(const float4*)(gp + 1024 + q * 4);
        float4 go = *(const float4*)(gp + 1536 + q * 4);
        float4 co = *(const float4*)(cr + q * 4);
        float4 hv, cv;
        __nv_bfloat16 bh4[4], bl4[4];
#pragma unroll
        for (int e = 0; e < 4; e++) {
            int hc = hb + q * 4 + e;
            float xi = gsm[row * 132 + hc]      + ((const float*)&gi)[e];
            float xf = gsm[row * 132 + 32 + hc] + ((const float*)&gf)[e];
            float xg = gsm[row * 132 + 64 + hc] + ((const float*)&gg)[e];
            float xo = gsm[row * 132 + 96 + hc] + ((const float*)&go)[e];
            float I = 1.f / (1.f + __expf(-xi));
            float F = 1.f / (1.f + __expf(-xf));
            float Gv = tanhf(xg);
            float O = 1.f / (1.f + __expf(-xo));
            float cn = F * ((const float*)&co)[e] + I * Gv;
            float hn = O * tanhf(cn);
            ((float*)&cv)[e] = cn;
            ((float*)&hv)[e] = hn;
            bh4[e] = __float2bfloat16(hn);
            bl4[e] = __float2bfloat16(hn - __bfloat162float(bh4[e]));
        }
        *(float4*)(hp + q * 4) = hv;
        *(float4*)(cp + q * 4) = cv;
        __nv_bfloat162 p0; p0.x = bh4[0]; p0.y = bh4[1];
        __nv_bfloat162 p1; p1.x = bh4[2]; p1.y = bh4[3];
        __nv_bfloat162 p2; p2.x = bl4[0]; p2.y = bl4[1];
        __nv_bfloat162 p3; p3.x = bl4[2]; p3.y = bl4[3];
        *(__nv_bfloat162*)(hhp + q * 4)     = p0;
        *(__nv_bfloat162*)(hhp + q * 4 + 2) = p1;
        *(__nv_bfloat162*)(hlp + q * 4)     = p2;
        *(__nv_bfloat162*)(hlp + q * 4 + 2) = p3;
    }
}

// ---------------- head kernels -------------------------------------------------
__global__ void clstm_gather_r(const float* __restrict__ Ytop, float* __restrict__ r) {
    int b = blockIdx.x, i = blockIdx.y, h = threadIdx.x;
    r[(size_t)b * 1536 + i * H_DIM + h] =
        Ytop[((size_t)(T_LEN - 1) * R_ROWS + i * B_SZ + b) * H_DIM + h];
}

__global__ void clstm_bn(float* __restrict__ x, const float* __restrict__ gamma,
                         const float* __restrict__ beta, int N) {
    __shared__ float s1[256], s2[256];
    int col = blockIdx.x;
    float v = x[(size_t)threadIdx.x * N + col];
    s1[threadIdx.x] = v; s2[threadIdx.x] = v * v;
    __syncthreads();
    for (int s = 128; s > 0; s >>= 1) {
        if (threadIdx.x < s) {
            s1[threadIdx.x] += s1[threadIdx.x + s];
            s2[threadIdx.x] += s2[threadIdx.x + s];
        }
        __syncthreads();
    }
    float m = s1[0] * (1.f / 256.f);
    float var = s2[0] * (1.f / 256.f) - m * m;
    float inv = rsqrtf(var + 1e-3f);
    x[(size_t)threadIdx.x * N + col] = gamma[col] * (v - m) * inv + beta[col];
}

__global__ void clstm_gemm_head(const float* __restrict__ A, const float* __restrict__ W,
                                const float* __restrict__ bias, float* __restrict__ C,
                                int K, int N, int act) {
    int n = blockIdx.x * 128 + threadIdx.x;
    int m0 = blockIdx.y * 16;
    if (n >= N) return;
    float s[16];
#pragma unroll
    for (int mm = 0; mm < 16; mm++) s[mm] = bias[n];
    for (int k = 0; k < K; k++) {
        float w = W[(size_t)k * N + n];
#pragma unroll
        for (int mm = 0; mm < 16; mm++)
            s[mm] += A[(size_t)(m0 + mm) * K + k] * w;
    }
    const float alpha = 1.6732632423543772f, scale = 1.0507009873554805f;
#pragma unroll
    for (int mm = 0; mm < 16; mm++) {
        float v = s[mm];
        if (act) v = scale * (v > 0.f ? v : alpha * expm1f(v));
        C[(size_t)(m0 + mm) * N + n] = v;
    }
}

// ---------------- launch --------------------------------------------------------
extern "C" void kernel_launch(void* const* d_in, const int* in_sizes, int n_in,
                              void* d_out, int out_size) {
    const int* t1 = (const int*)d_in[0];
    const int* t2 = (const int*)d_in[1];
    const int* t3 = (const int*)d_in[2];
    const float* emb = (const float*)d_in[3];
    const float* Wx = (const float*)d_in[4];
    const float* Wh = (const float*)d_in[5];
    const float* bb = (const float*)d_in[6];
    const float* g1 = (const float*)d_in[7];
    const float* be1 = (const float*)d_in[8];
    const float* W1 = (const float*)d_in[9];
    const float* bd1 = (const float*)d_in[10];
    const float* g2 = (const float*)d_in[11];
    const float* be2 = (const float*)d_in[12];
    const float* W2 = (const float*)d_in[13];
    const float* bd2 = (const float*)d_in[14];
    const float* g3 = (const float*)d_in[15];
    const float* be3 = (const float*)d_in[16];
    const float* W3 = (const float*)d_in[17];
    const float* bd3 = (const float*)d_in[18];
    float* out = (float*)d_out;

    float *X, *Y, *G, *C, *R, *H1, *H2;
    __nv_bfloat16 *Phi, *Plo, *Hh, *Hl;
    cudaGetSymbolAddress((void**)&X, d_Xbuf);
    cudaGetSymbolAddress((void**)&Y, d_Ybuf);
    cudaGetSymbolAddress((void**)&G, d_Gbuf);
    cudaGetSymbolAddress((void**)&C, d_cst);
    cudaGetSymbolAddress((void**)&R, d_rbuf);
    cudaGetSymbolAddress((void**)&H1, d_h1buf);
    cudaGetSymbolAddress((void**)&H2, d_h2buf);
    cudaGetSymbolAddress((void**)&Phi, d_WhPhi);
    cudaGetSymbolAddress((void**)&Plo, d_WhPlo);
    cudaGetSymbolAddress((void**)&Hh, d_hhi);
    cudaGetSymbolAddress((void**)&Hl, d_hlo);
    __nv_bfloat16* Hhb[2] = { Hh, Hh + 393216 };
    __nv_bfloat16* Hlb[2] = { Hl, Hl + 393216 };

    cudaFuncSetAttribute(clstm_step_mma, cudaFuncAttributeMaxDynamicSharedMemorySize,
                         STEP_SMEM);

    clstm_embed<<<dim3(R_ROWS, T_LEN), 128>>>(t1, t2, t3, emb, X);
    clstm_makeWhP<<<dim3(64, 16, 3), dim3(32, 8)>>>(Wh, Phi, Plo);

    float* inb = X;
    float* outb = Y;
    for (int l = 0; l < 3; l++) {
        clstm_gemm_bias<<<dim3(G_COLS / 128, M_ALL / 128), 256>>>(
            inb, Wx + (size_t)l * H_DIM * G_COLS, bb + (size_t)l * G_COLS, G,
            M_ALL, G_COLS, H_DIM);
        cudaMemsetAsync(C, 0, (size_t)R_ROWS * H_DIM * sizeof(float), 0);
        cudaMemsetAsync(Hhb[0], 0, (size_t)R_ROWS * H_DIM * 2, 0);
        cudaMemsetAsync(Hlb[0], 0, (size_t)R_ROWS * H_DIM * 2, 0);
        for (int t = 0; t < T_LEN; t++) {
            clstm_step_mma<<<dim3(16, 6), 256, STEP_SMEM>>>(
                G + (size_t)t * R_ROWS * G_COLS,
                Hhb[t & 1], Hlb[t & 1],
                Phi + (size_t)l * G_COLS * H_DIM, Plo + (size_t)l * G_COLS * H_DIM,
                C, outb + (size_t)t * R_ROWS * H_DIM,
                Hhb[(t + 1) & 1], Hlb[(t + 1) & 1]);
        }
        float* tmp = inb; inb = outb; outb = tmp;
    }

    clstm_gather_r<<<dim3(B_SZ, 3), H_DIM>>>(inb, R);
    clstm_bn<<<1536, 256>>>(R, g1, be1, 1536);
    clstm_gemm_head<<<dim3(8, 16), 128>>>(R, W1, bd1, H1, 1536, 1024, 1);
    clstm_bn<<<1024, 256>>>(H1, g2, be2, 1024);
    clstm_gemm_head<<<dim3(1, 16), 128>>>(H1, W2, bd2, H2, 1024, H5, 1);
    clstm_bn<<<H5, 256>>>(H2, g3, be3, H5);
    clstm_gemm_head<<<dim3(1, 16), 128>>>(H2, W3, bd3, out, H5, 4, 0);
}

// round 6
// speedup vs baseline: 2.1923x; 1.4692x over previous
#include <cuda_runtime.h>
#include <cuda_bf16.h>
#include <math.h>
#include <stdint.h>
#include <stddef.h>

#define T_LEN 256
#define B_SZ  256
#define H_DIM 512
#define R_ROWS 768
#define G_COLS 2048
#define M_ALL  196608
#define H5 102
#define RH 393216            // R_ROWS * H_DIM

// ---------------- static device scratch --------------------------------------
__device__ float d_Gbuf[402653184];   // [T][768][2048] x@Wx + b
__device__ float d_cst[393216];       // cell state
__device__ float d_rbuf[393216];
__device__ float d_h1buf[262144];
__device__ float d_h2buf[26112];
__device__ __nv_bfloat16 d_WhPhi[3 * 2048 * 512];   // Wh permuted [n'][k] hi
__device__ __nv_bfloat16 d_WhPlo[3 * 2048 * 512];   // Wh permuted [n'][k] lo
__device__ __nv_bfloat16 d_WxThi[3 * 2048 * 512];   // Wx transposed [n][k] hi
__device__ __nv_bfloat16 d_WxTlo[3 * 2048 * 512];   // Wx transposed [n][k] lo
__device__ __nv_bfloat16 d_sAhi[100663296];         // [T][768][512] splits (ping)
__device__ __nv_bfloat16 d_sAlo[100663296];
__device__ __nv_bfloat16 d_sBhi[100663296];         // (pong)
__device__ __nv_bfloat16 d_sBlo[100663296];

// ---------------- helpers ------------------------------------------------------
__device__ __forceinline__ uint32_t smem_to_u32(const void* p) {
    uint32_t a;
    asm("{ .reg .u64 t; cvta.to.shared.u64 t, %1; cvt.u32.u64 %0, t; }"
        : "=r"(a) : "l"(p));
    return a;
}
__device__ __forceinline__ void ldmx4(uint32_t* r, uint32_t addr) {
    asm volatile("ldmatrix.sync.aligned.m8n8.x4.shared.b16 {%0,%1,%2,%3}, [%4];"
                 : "=r"(r[0]), "=r"(r[1]), "=r"(r[2]), "=r"(r[3]) : "r"(addr));
}
__device__ __forceinline__ void mma_bf16(float* c, const uint32_t* a,
                                         uint32_t b0, uint32_t b1) {
    asm volatile(
        "mma.sync.aligned.m16n8k16.row.col.f32.bf16.bf16.f32 "
        "{%0,%1,%2,%3}, {%4,%5,%6,%7}, {%8,%9}, {%0,%1,%2,%3};"
        : "+f"(c[0]), "+f"(c[1]), "+f"(c[2]), "+f"(c[3])
        : "r"(a[0]), "r"(a[1]), "r"(a[2]), "r"(a[3]), "r"(b0), "r"(b1));
}
#define CP_ASYNC16(dst, src) \
    asm volatile("cp.async.cg.shared.global [%0], [%1], 16;" :: "r"(dst), "l"(src))
#define CP_COMMIT()  asm volatile("cp.async.commit_group;" ::: "memory")
#define CP_WAIT0()   asm volatile("cp.async.wait_group 0;" ::: "memory")
#define CP_WAIT1()   asm volatile("cp.async.wait_group 1;" ::: "memory")

// SMEM stage layout (K-chunk 64, rows padded to 144B):
//   Ahi 64x144=9216 | Alo 9216 | Bhi 128x144=18432 | Blo 18432  -> 55296/stage
#define STAGE_B 55296
#define MMA_SMEM 110592

// ---------------- embedding gather + split -------------------------------------
__global__ void clstm_embed(const int* __restrict__ t1, const int* __restrict__ t2,
                            const int* __restrict__ t3, const float* __restrict__ emb,
                            __nv_bfloat16* __restrict__ Xhi,
                            __nv_bfloat16* __restrict__ Xlo) {
    int row = blockIdx.x, t = blockIdx.y;
    int text = row >> 8, b = row & 255;
    const int* tp = (text == 0) ? t1 : (text == 1 ? t2 : t3);
    int tok = tp[b * T_LEN + t];
    float4 v = ((const float4*)(emb + (size_t)tok * H_DIM))[threadIdx.x];
    size_t base = ((size_t)t * R_ROWS + row) * H_DIM + threadIdx.x * 4;
    float vv[4] = { v.x, v.y, v.z, v.w };
    __nv_bfloat16 h[4], l[4];
#pragma unroll
    for (int e = 0; e < 4; e++) {
        h[e] = __float2bfloat16(vv[e]);
        l[e] = __float2bfloat16(vv[e] - __bfloat162float(h[e]));
    }
    __nv_bfloat162 p0; p0.x = h[0]; p0.y = h[1];
    __nv_bfloat162 p1; p1.x = h[2]; p1.y = h[3];
    __nv_bfloat162 q0; q0.x = l[0]; q0.y = l[1];
    __nv_bfloat162 q1; q1.x = l[2]; q1.y = l[3];
    *(__nv_bfloat162*)(Xhi + base) = p0;
    *(__nv_bfloat162*)(Xhi + base + 2) = p1;
    *(__nv_bfloat162*)(Xlo + base) = q0;
    *(__nv_bfloat162*)(Xlo + base + 2) = q1;
}

// ---------------- W [k][n] -> [n'][k] bf16 split (optional gate permute) --------
__global__ void clstm_makeWsplit(const float* __restrict__ W,
                                 __nv_bfloat16* __restrict__ Phi,
                                 __nv_bfloat16* __restrict__ Plo, int permute) {
    __shared__ float tile[32][33];
    int n0 = blockIdx.x * 32, k0 = blockIdx.y * 32, l = blockIdx.z;
    const float* Wl = W + (size_t)l * H_DIM * G_COLS;
    int tx = threadIdx.x, ty = threadIdx.y;
#pragma unroll
    for (int it = 0; it < 4; it++)
        tile[ty + it * 8][tx] = Wl[(size_t)(k0 + ty + it * 8) * G_COLS + n0 + tx];
    __syncthreads();
    int s = n0 >> 9, cbb = (n0 >> 5) & 15;
    int np0 = permute ? (cbb * 128 + s * 32) : n0;
    __nv_bfloat16* ph = Phi + (size_t)l * G_COLS * H_DIM;
    __nv_bfloat16* pl = Plo + (size_t)l * G_COLS * H_DIM;
#pragma unroll
    for (int it = 0; it < 4; it++) {
        int nn = ty + it * 8;
        float v = tile[tx][nn];
        __nv_bfloat16 hi = __float2bfloat16(v);
        __nv_bfloat16 lo = __float2bfloat16(v - __bfloat162float(hi));
        ph[(size_t)(np0 + nn) * H_DIM + k0 + tx] = hi;
        pl[(size_t)(np0 + nn) * H_DIM + k0 + tx] = lo;
    }
}

// ---------------- HMMA batched gate GEMM ---------------------------------------
// grid (16, 3072): 64-row x 128-col tiles over [196608, 2048], K=512.
// G = Ahi*Bhi + Ahi*Blo + Alo*Bhi + bias (fp32 accum).
__global__ void __launch_bounds__(256, 2)
clstm_gemm_mma(const __nv_bfloat16* __restrict__ Ahi, const __nv_bfloat16* __restrict__ Alo,
               const __nv_bfloat16* __restrict__ Bhi, const __nv_bfloat16* __restrict__ Blo,
               const float* __restrict__ bias, float* __restrict__ G) {
    extern __shared__ char smem[];
    const uint32_t sb = smem_to_u32(smem);
    const int tid = threadIdx.x, lane = tid & 31, w = tid >> 5;
    const int cb = blockIdx.x;
    const size_t bm = (size_t)blockIdx.y * 64;
    const __nv_bfloat16* asrc[2] = { Ahi + bm * H_DIM, Alo + bm * H_DIM };
    const __nv_bfloat16* bsrc[2] = { Bhi + (size_t)(cb * 128) * H_DIM,
                                     Blo + (size_t)(cb * 128) * H_DIM };
    const int lr = tid >> 3, lq = tid & 7;

    auto load_chunk = [&](int c, int s) {
        uint32_t stg = sb + (uint32_t)s * STAGE_B;
#pragma unroll
        for (int p = 0; p < 2; p++) {
            const __nv_bfloat16* gb = asrc[p] + c * 64;
            uint32_t sd = stg + p * 9216;
#pragma unroll
            for (int i = 0; i < 2; i++) {
                int r = lr + i * 32;
                CP_ASYNC16(sd + r * 144 + lq * 16,
                           (const void*)(gb + (size_t)r * H_DIM + lq * 8));
            }
        }
#pragma unroll
        for (int p = 0; p < 2; p++) {
            const __nv_bfloat16* gb = bsrc[p] + c * 64;
            uint32_t sd = stg + 18432 + p * 18432;
#pragma unroll
            for (int i = 0; i < 4; i++) {
                int r = lr + i * 32;
                CP_ASYNC16(sd + r * 144 + lq * 16,
                           (const void*)(gb + (size_t)r * H_DIM + lq * 8));
            }
        }
        CP_COMMIT();
    };

    const int m0 = (w >> 1) * 16, n0 = (w & 1) * 64;
    const int arow = (lane & 7) + ((lane & 8) ? 8 : 0);
    const int akq  = (lane & 16) ? 16 : 0;
    const int brow = (lane & 7) + ((lane & 16) ? 8 : 0);
    const int bkq  = (lane & 8) ? 16 : 0;

    float acc[8][4];
#pragma unroll
    for (int nt = 0; nt < 8; nt++)
#pragma unroll
        for (int e = 0; e < 4; e++) acc[nt][e] = 0.f;

    load_chunk(0, 0);
    for (int c = 0; c < 8; c++) {
        if (c < 7) { load_chunk(c + 1, (c + 1) & 1); CP_WAIT1(); }
        else       { CP_WAIT0(); }
        __syncthreads();
        uint32_t stg = sb + (uint32_t)(c & 1) * STAGE_B;
        uint32_t aH = stg, aL = stg + 9216, bH = stg + 18432, bL = stg + 36864;
#pragma unroll
        for (int ks = 0; ks < 4; ks++) {
            int kb = ks * 32;
            uint32_t ah[4], al[4], bh[4][4], bl[4][4];
            ldmx4(ah, aH + (m0 + arow) * 144 + kb + akq);
            ldmx4(al, aL + (m0 + arow) * 144 + kb + akq);
#pragma unroll
            for (int p = 0; p < 4; p++) {
                ldmx4(bh[p], bH + (n0 + p * 16 + brow) * 144 + kb + bkq);
                ldmx4(bl[p], bL + (n0 + p * 16 + brow) * 144 + kb + bkq);
            }
#pragma unroll
            for (int nt = 0; nt < 8; nt++) {
                uint32_t h0 = bh[nt >> 1][(nt & 1) * 2], h1 = bh[nt >> 1][(nt & 1) * 2 + 1];
                uint32_t l0 = bl[nt >> 1][(nt & 1) * 2], l1 = bl[nt >> 1][(nt & 1) * 2 + 1];
                mma_bf16(acc[nt], ah, h0, h1);
                mma_bf16(acc[nt], ah, l0, l1);
                mma_bf16(acc[nt], al, h0, h1);
            }
        }
        __syncthreads();
    }

    float* gsm = (float*)smem;     // [64][132]
#pragma unroll
    for (int nt = 0; nt < 8; nt++) {
        int row = m0 + (lane >> 2);
        int col = n0 + nt * 8 + (lane & 3) * 2;
        gsm[row * 132 + col]     = acc[nt][0];
        gsm[row * 132 + col + 1] = acc[nt][1];
        gsm[(row + 8) * 132 + col]     = acc[nt][2];
        gsm[(row + 8) * 132 + col + 1] = acc[nt][3];
    }
    __syncthreads();

    int row = tid >> 2, c0 = (tid & 3) * 32;
    float* gp = G + (bm + row) * G_COLS + cb * 128;
#pragma unroll
    for (int q = 0; q < 8; q++) {
        int col = c0 + q * 4;
        float4 v = *(float4*)(gsm + row * 132 + col);
        float4 bv = *(const float4*)(bias + cb * 128 + col);
        v.x += bv.x; v.y += bv.y; v.z += bv.z; v.w += bv.w;
        *(float4*)(gp + col) = v;
    }
}

// ---------------- HMMA recurrent step (64-row tiles, 192 CTAs) ------------------
// grid (16, 12). Tile 64 rows x 128 gate cols (permuted: 4 gate strips x 32).
__global__ void __launch_bounds__(256, 2)
clstm_step_mma(const float* __restrict__ Gt,
               const __nv_bfloat16* __restrict__ Ahi, const __nv_bfloat16* __restrict__ Alo,
               const __nv_bfloat16* __restrict__ Bhi, const __nv_bfloat16* __restrict__ Blo,
               float* __restrict__ cst,
               __nv_bfloat16* __restrict__ Hhi, __nv_bfloat16* __restrict__ Hlo,
               int t0) {
    extern __shared__ char smem[];
    const uint32_t sb = smem_to_u32(smem);
    const int tid = threadIdx.x, lane = tid & 31, w = tid >> 5;
    const int cb = blockIdx.x;
    const size_t bm = (size_t)blockIdx.y * 64;
    const __nv_bfloat16* asrc[2] = { Ahi + bm * H_DIM, Alo + bm * H_DIM };
    const __nv_bfloat16* bsrc[2] = { Bhi + (size_t)(cb * 128) * H_DIM,
                                     Blo + (size_t)(cb * 128) * H_DIM };
    const int lr = tid >> 3, lq = tid & 7;

    auto load_chunk = [&](int c, int s) {
        uint32_t stg = sb + (uint32_t)s * STAGE_B;
#pragma unroll
        for (int p = 0; p < 2; p++) {
            const __nv_bfloat16* gb = asrc[p] + c * 64;
            uint32_t sd = stg + p * 9216;
#pragma unroll
            for (int i = 0; i < 2; i++) {
                int r = lr + i * 32;
                CP_ASYNC16(sd + r * 144 + lq * 16,
                           (const void*)(gb + (size_t)r * H_DIM + lq * 8));
            }
        }
#pragma unroll
        for (int p = 0; p < 2; p++) {
            const __nv_bfloat16* gb = bsrc[p] + c * 64;
            uint32_t sd = stg + 18432 + p * 18432;
#pragma unroll
            for (int i = 0; i < 4; i++) {
                int r = lr + i * 32;
                CP_ASYNC16(sd + r * 144 + lq * 16,
                           (const void*)(gb + (size_t)r * H_DIM + lq * 8));
            }
        }
        CP_COMMIT();
    };

    const int m0 = (w >> 1) * 16, n0 = (w & 1) * 64;
    const int arow = (lane & 7) + ((lane & 8) ? 8 : 0);
    const int akq  = (lane & 16) ? 16 : 0;
    const int brow = (lane & 7) + ((lane & 16) ? 8 : 0);
    const int bkq  = (lane & 8) ? 16 : 0;

    float acc[8][4];
#pragma unroll
    for (int nt = 0; nt < 8; nt++)
#pragma unroll
        for (int e = 0; e < 4; e++) acc[nt][e] = 0.f;

    if (!t0) {
        load_chunk(0, 0);
        for (int c = 0; c < 8; c++) {
            if (c < 7) { load_chunk(c + 1, (c + 1) & 1); CP_WAIT1(); }
            else       { CP_WAIT0(); }
            __syncthreads();
            uint32_t stg = sb + (uint32_t)(c & 1) * STAGE_B;
            uint32_t aH = stg, aL = stg + 9216, bH = stg + 18432, bL = stg + 36864;
#pragma unroll
            for (int ks = 0; ks < 4; ks++) {
                int kb = ks * 32;
                uint32_t ah[4], al[4], bh[4][4], bl[4][4];
                ldmx4(ah, aH + (m0 + arow) * 144 + kb + akq);
                ldmx4(al, aL + (m0 + arow) * 144 + kb + akq);
#pragma unroll
                for (int p = 0; p < 4; p++) {
                    ldmx4(bh[p], bH + (n0 + p * 16 + brow) * 144 + kb + bkq);
                    ldmx4(bl[p], bL + (n0 + p * 16 + brow) * 144 + kb + bkq);
                }
#pragma unroll
                for (int nt = 0; nt < 8; nt++) {
                    uint32_t h0 = bh[nt >> 1][(nt & 1) * 2], h1 = bh[nt >> 1][(nt & 1) * 2 + 1];
                    uint32_t l0 = bl[nt >> 1][(nt & 1) * 2], l1 = bl[nt >> 1][(nt & 1) * 2 + 1];
                    mma_bf16(acc[nt], ah, h0, h1);
                    mma_bf16(acc[nt], ah, l0, l1);
                    mma_bf16(acc[nt], al, h0, h1);
                }
            }
            __syncthreads();
        }
    }

    float* gsm = (float*)smem;     // [64][132]
#pragma unroll
    for (int nt = 0; nt < 8; nt++) {
        int row = m0 + (lane >> 2);
        int col = n0 + nt * 8 + (lane & 3) * 2;
        gsm[row * 132 + col]     = acc[nt][0];
        gsm[row * 132 + col + 1] = acc[nt][1];
        gsm[(row + 8) * 132 + col]     = acc[nt][2];
        gsm[(row + 8) * 132 + col + 1] = acc[nt][3];
    }
    __syncthreads();

    // fused LSTM epilogue: 64 rows x 32 h-cols, 8 per thread
    const int row = tid >> 2, hb = (tid & 3) * 8;
    const size_t grow = bm + row;
    const int hc0 = cb * 32 + hb;
    const float* gp = Gt + grow * G_COLS + hc0;
    const float* cr = cst + grow * H_DIM + hc0;
    float* cp = cst + grow * H_DIM + hc0;
    __nv_bfloat16* hhp = Hhi + grow * H_DIM + hc0;
    __nv_bfloat16* hlp = Hlo + grow * H_DIM + hc0;
#pragma unroll
    for (int q = 0; q < 2; q++) {
        float4 gi = *(const float4*)(gp + q * 4);
        float4 gf = *(const float4*)(gp + 512 + q * 4);
        float4 gg = *(const float4*)(gp + 1024 + q * 4);
        float4 go = *(const float4*)(gp + 1536 + q * 4);
        float4 co = *(const float4*)(cr + q * 4);
        float4 cv;
        __nv_bfloat16 bh4[4], bl4[4];
#pragma unroll
        for (int e = 0; e < 4; e++) {
            int lc = hb + q * 4 + e;
            float xi = gsm[row * 132 + lc]      + ((const float*)&gi)[e];
            float xf = gsm[row * 132 + 32 + lc] + ((const float*)&gf)[e];
            float xg = gsm[row * 132 + 64 + lc] + ((const float*)&gg)[e];
            float xo = gsm[row * 132 + 96 + lc] + ((const float*)&go)[e];
            float I = 1.f / (1.f + __expf(-xi));
            float F = 1.f / (1.f + __expf(-xf));
            float Gv = tanhf(xg);
            float O = 1.f / (1.f + __expf(-xo));
            float cn = F * ((const float*)&co)[e] + I * Gv;
            float hn = O * tanhf(cn);
            ((float*)&cv)[e] = cn;
            bh4[e] = __float2bfloat16(hn);
            bl4[e] = __float2bfloat16(hn - __bfloat162float(bh4[e]));
        }
        *(float4*)(cp + q * 4) = cv;
        __nv_bfloat162 p0; p0.x = bh4[0]; p0.y = bh4[1];
        __nv_bfloat162 p1; p1.x = bh4[2]; p1.y = bh4[3];
        __nv_bfloat162 q0; q0.x = bl4[0]; q0.y = bl4[1];
        __nv_bfloat162 q1; q1.x = bl4[2]; q1.y = bl4[3];
        *(__nv_bfloat162*)(hhp + q * 4)     = p0;
        *(__nv_bfloat162*)(hhp + q * 4 + 2) = p1;
        *(__nv_bfloat162*)(hlp + q * 4)     = q0;
        *(__nv_bfloat162*)(hlp + q * 4 + 2) = q1;
    }
}

// ---------------- head kernels -------------------------------------------------
__global__ void clstm_gather_r(const __nv_bfloat16* __restrict__ Hhi,
                               const __nv_bfloat16* __restrict__ Hlo,
                               float* __restrict__ r) {
    int b = blockIdx.x, i = blockIdx.y, h = threadIdx.x;
    size_t idx = ((size_t)(T_LEN - 1) * R_ROWS + i * B_SZ + b) * H_DIM + h;
    r[(size_t)b * 1536 + i * H_DIM + h] =
        __bfloat162float(Hhi[idx]) + __bfloat162float(Hlo[idx]);
}

__global__ void clstm_bn(float* __restrict__ x, const float* __restrict__ gamma,
                         const float* __restrict__ beta, int N) {
    __shared__ float s1[256], s2[256];
    int col = blockIdx.x;
    float v = x[(size_t)threadIdx.x * N + col];
    s1[threadIdx.x] = v; s2[threadIdx.x] = v * v;
    __syncthreads();
    for (int s = 128; s > 0; s >>= 1) {
        if (threadIdx.x < s) {
            s1[threadIdx.x] += s1[threadIdx.x + s];
            s2[threadIdx.x] += s2[threadIdx.x + s];
        }
        __syncthreads();
    }
    float m = s1[0] * (1.f / 256.f);
    float var = s2[0] * (1.f / 256.f) - m * m;
    float inv = rsqrtf(var + 1e-3f);
    x[(size_t)threadIdx.x * N + col] = gamma[col] * (v - m) * inv + beta[col];
}

__global__ void clstm_gemm_head(const float* __restrict__ A, const float* __restrict__ W,
                                const float* __restrict__ bias, float* __restrict__ C,
                                int K, int N, int act) {
    int n = blockIdx.x * 128 + threadIdx.x;
    int m0 = blockIdx.y * 16;
    if (n >= N) return;
    float s[16];
#pragma unroll
    for (int mm = 0; mm < 16; mm++) s[mm] = bias[n];
    for (int k = 0; k < K; k++) {
        float w = W[(size_t)k * N + n];
#pragma unroll
        for (int mm = 0; mm < 16; mm++)
            s[mm] += A[(size_t)(m0 + mm) * K + k] * w;
    }
    const float alpha = 1.6732632423543772f, scale = 1.0507009873554805f;
#pragma unroll
    for (int mm = 0; mm < 16; mm++) {
        float v = s[mm];
        if (act) v = scale * (v > 0.f ? v : alpha * expm1f(v));
        C[(size_t)(m0 + mm) * N + n] = v;
    }
}

// ---------------- launch --------------------------------------------------------
extern "C" void kernel_launch(void* const* d_in, const int* in_sizes, int n_in,
                              void* d_out, int out_size) {
    const int* t1 = (const int*)d_in[0];
    const int* t2 = (const int*)d_in[1];
    const int* t3 = (const int*)d_in[2];
    const float* emb = (const float*)d_in[3];
    const float* Wx = (const float*)d_in[4];
    const float* Wh = (const float*)d_in[5];
    const float* bb = (const float*)d_in[6];
    const float* g1 = (const float*)d_in[7];
    const float* be1 = (const float*)d_in[8];
    const float* W1 = (const float*)d_in[9];
    const float* bd1 = (const float*)d_in[10];
    const float* g2 = (const float*)d_in[11];
    const float* be2 = (const float*)d_in[12];
    const float* W2 = (const float*)d_in[13];
    const float* bd2 = (const float*)d_in[14];
    const float* g3 = (const float*)d_in[15];
    const float* be3 = (const float*)d_in[16];
    const float* W3 = (const float*)d_in[17];
    const float* bd3 = (const float*)d_in[18];
    float* out = (float*)d_out;

    float *G, *C, *R, *H1, *H2;
    __nv_bfloat16 *WhPh, *WhPl, *WxTh, *WxTl, *sAh, *sAl, *sBh, *sBl;
    cudaGetSymbolAddress((void**)&G, d_Gbuf);
    cudaGetSymbolAddress((void**)&C, d_cst);
    cudaGetSymbolAddress((void**)&R, d_rbuf);
    cudaGetSymbolAddress((void**)&H1, d_h1buf);
    cudaGetSymbolAddress((void**)&H2, d_h2buf);
    cudaGetSymbolAddress((void**)&WhPh, d_WhPhi);
    cudaGetSymbolAddress((void**)&WhPl, d_WhPlo);
    cudaGetSymbolAddress((void**)&WxTh, d_WxThi);
    cudaGetSymbolAddress((void**)&WxTl, d_WxTlo);
    cudaGetSymbolAddress((void**)&sAh, d_sAhi);
    cudaGetSymbolAddress((void**)&sAl, d_sAlo);
    cudaGetSymbolAddress((void**)&sBh, d_sBhi);
    cudaGetSymbolAddress((void**)&sBl, d_sBlo);

    cudaFuncSetAttribute(clstm_gemm_mma, cudaFuncAttributeMaxDynamicSharedMemorySize,
                         MMA_SMEM);
    cudaFuncSetAttribute(clstm_step_mma, cudaFuncAttributeMaxDynamicSharedMemorySize,
                         MMA_SMEM);

    // embedding (with bf16 split) and weight preprocessing
    clstm_embed<<<dim3(R_ROWS, T_LEN), 128>>>(t1, t2, t3, emb, sAh, sAl);
    clstm_makeWsplit<<<dim3(64, 16, 3), dim3(32, 8)>>>(Wh, WhPh, WhPl, 1);
    clstm_makeWsplit<<<dim3(64, 16, 3), dim3(32, 8)>>>(Wx, WxTh, WxTl, 0);

    __nv_bfloat16 *inH = sAh, *inL = sAl, *outH = sBh, *outL = sBl;
    for (int l = 0; l < 3; l++) {
        size_t woff = (size_t)l * G_COLS * H_DIM;
        clstm_gemm_mma<<<dim3(16, M_ALL / 64), 256, MMA_SMEM>>>(
            inH, inL, WxTh + woff, WxTl + woff, bb + (size_t)l * G_COLS, G);
        cudaMemsetAsync(C, 0, (size_t)RH * sizeof(float), 0);
        for (int t = 0; t < T_LEN; t++) {
            clstm_step_mma<<<dim3(16, 12), 256, MMA_SMEM>>>(
                G + (size_t)t * R_ROWS * G_COLS,
                outH + (size_t)(t > 0 ? t - 1 : 0) * RH,
                outL + (size_t)(t > 0 ? t - 1 : 0) * RH,
                WhPh + woff, WhPl + woff, C,
                outH + (size_t)t * RH, outL + (size_t)t * RH, t == 0 ? 1 : 0);
        }
        __nv_bfloat16* tm;
        tm = inH; inH = outH; outH = tm;
        tm = inL; inL = outL; outL = tm;
    }

    // head
    clstm_gather_r<<<dim3(B_SZ, 3), H_DIM>>>(inH, inL, R);
    clstm_bn<<<1536, 256>>>(R, g1, be1, 1536);
    clstm_gemm_head<<<dim3(8, 16), 128>>>(R, W1, bd1, H1, 1536, 1024, 1);
    clstm_bn<<<1024, 256>>>(H1, g2, be2, 1024);
    clstm_gemm_head<<<dim3(1, 16), 128>>>(H1, W2, bd2, H2, 1024, H5, 1);
    clstm_bn<<<H5, 256>>>(H2, g3, be3, H5);
    clstm_gemm_head<<<dim3(1, 16), 128>>>(H2, W3, bd3, out, H5, 4, 0);
}

// round 7
// speedup vs baseline: 2.4071x; 1.0980x over previous
#include <cuda_runtime.h>
#include <cuda_bf16.h>
#include <math.h>
#include <stdint.h>
#include <stddef.h>

#define T_LEN 256
#define B_SZ  256
#define H_DIM 512
#define R_ROWS 768
#define G_COLS 2048
#define M_ALL  196608
#define V_SZ   32000
#define H5 102
#define RH 393216            // R_ROWS * H_DIM

// ---------------- static device scratch --------------------------------------
__device__ float d_Gbuf[402653184];   // [T][768][2048] h@Wx + b (layers 2,3)
__device__ float d_tab[65536000];     // [32000][2048] emb@Wx0 + b0
__device__ float d_cst[393216];
__device__ float d_rbuf[393216];
__device__ float d_h1buf[262144];
__device__ float d_h2buf[26112];
__device__ int   d_toks[196608];      // [3][256][256]
__device__ __nv_bfloat16 d_Ehi[16384000];           // emb split [32000][512]
__device__ __nv_bfloat16 d_Elo[16384000];
__device__ __nv_bfloat16 d_WhPhi[3 * 2048 * 512];   // Wh permuted [n'][k] hi
__device__ __nv_bfloat16 d_WhPlo[3 * 2048 * 512];
__device__ __nv_bfloat16 d_WxThi[3 * 2048 * 512];   // Wx transposed [n][k] hi
__device__ __nv_bfloat16 d_WxTlo[3 * 2048 * 512];
__device__ __nv_bfloat16 d_sAhi[100663296];         // h seq splits (ping)
__device__ __nv_bfloat16 d_sAlo[100663296];
__device__ __nv_bfloat16 d_sBhi[100663296];         // (pong)
__device__ __nv_bfloat16 d_sBlo[100663296];

// ---------------- helpers ------------------------------------------------------
__device__ __forceinline__ uint32_t smem_to_u32(const void* p) {
    uint32_t a;
    asm("{ .reg .u64 t; cvta.to.shared.u64 t, %1; cvt.u32.u64 %0, t; }"
        : "=r"(a) : "l"(p));
    return a;
}
__device__ __forceinline__ void ldmx4(uint32_t* r, uint32_t addr) {
    asm volatile("ldmatrix.sync.aligned.m8n8.x4.shared.b16 {%0,%1,%2,%3}, [%4];"
                 : "=r"(r[0]), "=r"(r[1]), "=r"(r[2]), "=r"(r[3]) : "r"(addr));
}
__device__ __forceinline__ void mma_bf16(float* c, const uint32_t* a,
                                         uint32_t b0, uint32_t b1) {
    asm volatile(
        "mma.sync.aligned.m16n8k16.row.col.f32.bf16.bf16.f32 "
        "{%0,%1,%2,%3}, {%4,%5,%6,%7}, {%8,%9}, {%0,%1,%2,%3};"
        : "+f"(c[0]), "+f"(c[1]), "+f"(c[2]), "+f"(c[3])
        : "r"(a[0]), "r"(a[1]), "r"(a[2]), "r"(a[3]), "r"(b0), "r"(b1));
}
#define CP_ASYNC16(dst, src) \
    asm volatile("cp.async.cg.shared.global [%0], [%1], 16;" :: "r"(dst), "l"(src))
#define CP_COMMIT()  asm volatile("cp.async.commit_group;" ::: "memory")
#define CP_WAIT0()   asm volatile("cp.async.wait_group 0;" ::: "memory")
#define CP_WAIT1()   asm volatile("cp.async.wait_group 1;" ::: "memory")

// SMEM stage: Ahi 64x144 | Alo | Bhi 128x144 | Blo  -> 55296 B/stage, 2 stages
#define STAGE_B 55296
#define MMA_SMEM 110592

// ---------------- emb -> bf16 split ---------------------------------------------
__global__ void clstm_splitemb(const float* __restrict__ emb,
                               __nv_bfloat16* __restrict__ Ehi,
                               __nv_bfloat16* __restrict__ Elo) {
    size_t base = (size_t)blockIdx.x * H_DIM + threadIdx.x * 4;
    float4 v = *(const float4*)(emb + base);
    float vv[4] = { v.x, v.y, v.z, v.w };
#pragma unroll
    for (int e = 0; e < 4; e++) {
        __nv_bfloat16 h = __float2bfloat16(vv[e]);
        Ehi[base + e] = h;
        Elo[base + e] = __float2bfloat16(vv[e] - __bfloat162float(h));
    }
}

// ---------------- W [k][n] -> [n'][k] bf16 split (optional gate permute) --------
__global__ void clstm_makeWsplit(const float* __restrict__ W,
                                 __nv_bfloat16* __restrict__ Phi,
                                 __nv_bfloat16* __restrict__ Plo, int permute) {
    __shared__ float tile[32][33];
    int n0 = blockIdx.x * 32, k0 = blockIdx.y * 32, l = blockIdx.z;
    const float* Wl = W + (size_t)l * H_DIM * G_COLS;
    int tx = threadIdx.x, ty = threadIdx.y;
#pragma unroll
    for (int it = 0; it < 4; it++)
        tile[ty + it * 8][tx] = Wl[(size_t)(k0 + ty + it * 8) * G_COLS + n0 + tx];
    __syncthreads();
    int s = n0 >> 9, cbb = (n0 >> 5) & 15;
    int np0 = permute ? (cbb * 128 + s * 32) : n0;
    __nv_bfloat16* ph = Phi + (size_t)l * G_COLS * H_DIM;
    __nv_bfloat16* pl = Plo + (size_t)l * G_COLS * H_DIM;
#pragma unroll
    for (int it = 0; it < 4; it++) {
        int nn = ty + it * 8;
        float v = tile[tx][nn];
        __nv_bfloat16 hi = __float2bfloat16(v);
        __nv_bfloat16 lo = __float2bfloat16(v - __bfloat162float(hi));
        ph[(size_t)(np0 + nn) * H_DIM + k0 + tx] = hi;
        pl[(size_t)(np0 + nn) * H_DIM + k0 + tx] = lo;
    }
}

// ---------------- HMMA batched GEMM (bias epilogue) -----------------------------
// 64-row x 128-col tiles, K=512. G = Ahi*Bhi + Ahi*Blo + Alo*Bhi + bias.
__global__ void __launch_bounds__(256, 2)
clstm_gemm_mma(const __nv_bfloat16* __restrict__ Ahi, const __nv_bfloat16* __restrict__ Alo,
               const __nv_bfloat16* __restrict__ Bhi, const __nv_bfloat16* __restrict__ Blo,
               const float* __restrict__ bias, float* __restrict__ G) {
    extern __shared__ char smem[];
    const uint32_t sb = smem_to_u32(smem);
    const int tid = threadIdx.x, lane = tid & 31, w = tid >> 5;
    const int cb = blockIdx.x;
    const size_t bm = (size_t)blockIdx.y * 64;
    const __nv_bfloat16* asrc[2] = { Ahi + bm * H_DIM, Alo + bm * H_DIM };
    const __nv_bfloat16* bsrc[2] = { Bhi + (size_t)(cb * 128) * H_DIM,
                                     Blo + (size_t)(cb * 128) * H_DIM };
    const int lr = tid >> 3, lq = tid & 7;

    auto load_chunk = [&](int c, int s) {
        uint32_t stg = sb + (uint32_t)s * STAGE_B;
#pragma unroll
        for (int p = 0; p < 2; p++) {
            const __nv_bfloat16* gb = asrc[p] + c * 64;
            uint32_t sd = stg + p * 9216;
#pragma unroll
            for (int i = 0; i < 2; i++) {
                int r = lr + i * 32;
                CP_ASYNC16(sd + r * 144 + lq * 16,
                           (const void*)(gb + (size_t)r * H_DIM + lq * 8));
            }
        }
#pragma unroll
        for (int p = 0; p < 2; p++) {
            const __nv_bfloat16* gb = bsrc[p] + c * 64;
            uint32_t sd = stg + 18432 + p * 18432;
#pragma unroll
            for (int i = 0; i < 4; i++) {
                int r = lr + i * 32;
                CP_ASYNC16(sd + r * 144 + lq * 16,
                           (const void*)(gb + (size_t)r * H_DIM + lq * 8));
            }
        }
        CP_COMMIT();
    };

    const int m0 = (w >> 1) * 16, n0 = (w & 1) * 64;
    const int arow = (lane & 7) + ((lane & 8) ? 8 : 0);
    const int akq  = (lane & 16) ? 16 : 0;
    const int brow = (lane & 7) + ((lane & 16) ? 8 : 0);
    const int bkq  = (lane & 8) ? 16 : 0;

    float acc[8][4];
#pragma unroll
    for (int nt = 0; nt < 8; nt++)
#pragma unroll
        for (int e = 0; e < 4; e++) acc[nt][e] = 0.f;

    load_chunk(0, 0);
    for (int c = 0; c < 8; c++) {
        if (c < 7) { load_chunk(c + 1, (c + 1) & 1); CP_WAIT1(); }
        else       { CP_WAIT0(); }
        __syncthreads();
        uint32_t stg = sb + (uint32_t)(c & 1) * STAGE_B;
        uint32_t aH = stg, aL = stg + 9216, bH = stg + 18432, bL = stg + 36864;
#pragma unroll
        for (int ks = 0; ks < 4; ks++) {
            int kb = ks * 32;
            uint32_t ah[4], al[4], bh[4][4], bl[4][4];
            ldmx4(ah, aH + (m0 + arow) * 144 + kb + akq);
            ldmx4(al, aL + (m0 + arow) * 144 + kb + akq);
#pragma unroll
            for (int p = 0; p < 4; p++) {
                ldmx4(bh[p], bH + (n0 + p * 16 + brow) * 144 + kb + bkq);
                ldmx4(bl[p], bL + (n0 + p * 16 + brow) * 144 + kb + bkq);
            }
            // plane-major: consecutive mma hit different accumulators
#pragma unroll
            for (int nt = 0; nt < 8; nt++)
                mma_bf16(acc[nt], ah, bh[nt >> 1][(nt & 1) * 2], bh[nt >> 1][(nt & 1) * 2 + 1]);
#pragma unroll
            for (int nt = 0; nt < 8; nt++)
                mma_bf16(acc[nt], ah, bl[nt >> 1][(nt & 1) * 2], bl[nt >> 1][(nt & 1) * 2 + 1]);
#pragma unroll
            for (int nt = 0; nt < 8; nt++)
                mma_bf16(acc[nt], al, bh[nt >> 1][(nt & 1) * 2], bh[nt >> 1][(nt & 1) * 2 + 1]);
        }
        __syncthreads();
    }

    float* gsm = (float*)smem;     // [64][132]
#pragma unroll
    for (int nt = 0; nt < 8; nt++) {
        int row = m0 + (lane >> 2);
        int col = n0 + nt * 8 + (lane & 3) * 2;
        gsm[row * 132 + col]     = acc[nt][0];
        gsm[row * 132 + col + 1] = acc[nt][1];
        gsm[(row + 8) * 132 + col]     = acc[nt][2];
        gsm[(row + 8) * 132 + col + 1] = acc[nt][3];
    }
    __syncthreads();

    int row = tid >> 2, c0 = (tid & 3) * 32;
    float* gp = G + (bm + row) * G_COLS + cb * 128;
#pragma unroll
    for (int q = 0; q < 8; q++) {
        int col = c0 + q * 4;
        float4 v = *(float4*)(gsm + row * 132 + col);
        float4 bv = *(const float4*)(bias + cb * 128 + col);
        v.x += bv.x; v.y += bv.y; v.z += bv.z; v.w += bv.w;
        *(float4*)(gp + col) = v;
    }
}

// ---------------- HMMA recurrent step -------------------------------------------
// grid (16, 12). Tile 64 rows x 128 gate cols (permuted 4x32 strips).
// Layer 1: gate precompute gathered from tab[token]; layers 2-3: from Gt.
__global__ void __launch_bounds__(256, 2)
clstm_step_mma(const float* __restrict__ Gt,
               const int* __restrict__ toks, const float* __restrict__ tab, int tstep,
               const __nv_bfloat16* __restrict__ Ahi, const __nv_bfloat16* __restrict__ Alo,
               const __nv_bfloat16* __restrict__ Bhi, const __nv_bfloat16* __restrict__ Blo,
               float* __restrict__ cst,
               __nv_bfloat16* __restrict__ Hhi, __nv_bfloat16* __restrict__ Hlo,
               int t0) {
    extern __shared__ char smem[];
    const uint32_t sb = smem_to_u32(smem);
    const int tid = threadIdx.x, lane = tid & 31, w = tid >> 5;
    const int cb = blockIdx.x;
    const size_t bm = (size_t)blockIdx.y * 64;
    const __nv_bfloat16* asrc[2] = { Ahi + bm * H_DIM, Alo + bm * H_DIM };
    const __nv_bfloat16* bsrc[2] = { Bhi + (size_t)(cb * 128) * H_DIM,
                                     Blo + (size_t)(cb * 128) * H_DIM };
    const int lr = tid >> 3, lq = tid & 7;

    auto load_chunk = [&](int c, int s) {
        uint32_t stg = sb + (uint32_t)s * STAGE_B;
#pragma unroll
        for (int p = 0; p < 2; p++) {
            const __nv_bfloat16* gb = asrc[p] + c * 64;
            uint32_t sd = stg + p * 9216;
#pragma unroll
            for (int i = 0; i < 2; i++) {
                int r = lr + i * 32;
                CP_ASYNC16(sd + r * 144 + lq * 16,
                           (const void*)(gb + (size_t)r * H_DIM + lq * 8));
            }
        }
#pragma unroll
        for (int p = 0; p < 2; p++) {
            const __nv_bfloat16* gb = bsrc[p] + c * 64;
            uint32_t sd = stg + 18432 + p * 18432;
#pragma unroll
            for (int i = 0; i < 4; i++) {
                int r = lr + i * 32;
                CP_ASYNC16(sd + r * 144 + lq * 16,
                           (const void*)(gb + (size_t)r * H_DIM + lq * 8));
            }
        }
        CP_COMMIT();
    };

    const int m0 = (w >> 1) * 16, n0 = (w & 1) * 64;
    const int arow = (lane & 7) + ((lane & 8) ? 8 : 0);
    const int akq  = (lane & 16) ? 16 : 0;
    const int brow = (lane & 7) + ((lane & 16) ? 8 : 0);
    const int bkq  = (lane & 8) ? 16 : 0;

    float acc[8][4];
#pragma unroll
    for (int nt = 0; nt < 8; nt++)
#pragma unroll
        for (int e = 0; e < 4; e++) acc[nt][e] = 0.f;

    if (!t0) {
        load_chunk(0, 0);
        for (int c = 0; c < 8; c++) {
            if (c < 7) { load_chunk(c + 1, (c + 1) & 1); CP_WAIT1(); }
            else       { CP_WAIT0(); }
            __syncthreads();
            uint32_t stg = sb + (uint32_t)(c & 1) * STAGE_B;
            uint32_t aH = stg, aL = stg + 9216, bH = stg + 18432, bL = stg + 36864;
#pragma unroll
            for (int ks = 0; ks < 4; ks++) {
                int kb = ks * 32;
                uint32_t ah[4], al[4], bh[4][4], bl[4][4];
                ldmx4(ah, aH + (m0 + arow) * 144 + kb + akq);
                ldmx4(al, aL + (m0 + arow) * 144 + kb + akq);
#pragma unroll
                for (int p = 0; p < 4; p++) {
                    ldmx4(bh[p], bH + (n0 + p * 16 + brow) * 144 + kb + bkq);
                    ldmx4(bl[p], bL + (n0 + p * 16 + brow) * 144 + kb + bkq);
                }
#pragma unroll
                for (int nt = 0; nt < 8; nt++)
                    mma_bf16(acc[nt], ah, bh[nt >> 1][(nt & 1) * 2], bh[nt >> 1][(nt & 1) * 2 + 1]);
#pragma unroll
                for (int nt = 0; nt < 8; nt++)
                    mma_bf16(acc[nt], ah, bl[nt >> 1][(nt & 1) * 2], bl[nt >> 1][(nt & 1) * 2 + 1]);
#pragma unroll
                for (int nt = 0; nt < 8; nt++)
                    mma_bf16(acc[nt], al, bh[nt >> 1][(nt & 1) * 2], bh[nt >> 1][(nt & 1) * 2 + 1]);
            }
            __syncthreads();
        }
    }

    float* gsm = (float*)smem;     // [64][132]
#pragma unroll
    for (int nt = 0; nt < 8; nt++) {
        int row = m0 + (lane >> 2);
        int col = n0 + nt * 8 + (lane & 3) * 2;
        gsm[row * 132 + col]     = acc[nt][0];
        gsm[row * 132 + col + 1] = acc[nt][1];
        gsm[(row + 8) * 132 + col]     = acc[nt][2];
        gsm[(row + 8) * 132 + col + 1] = acc[nt][3];
    }
    __syncthreads();

    // fused LSTM epilogue: 64 rows x 32 h-cols, 8 per thread
    const int row = tid >> 2, hb = (tid & 3) * 8;
    const size_t grow = bm + row;
    const int hc0 = cb * 32 + hb;
    const float* gp;
    if (toks) {
        int tk = __ldg(toks + (((int)grow >> 8) << 16) + (((int)grow & 255) << 8) + tstep);
        gp = tab + (size_t)tk * G_COLS + hc0;
    } else {
        gp = Gt + grow * G_COLS + hc0;
    }
    const float* cr = cst + grow * H_DIM + hc0;
    float* cp = cst + grow * H_DIM + hc0;
    __nv_bfloat16* hhp = Hhi + grow * H_DIM + hc0;
    __nv_bfloat16* hlp = Hlo + grow * H_DIM + hc0;
#pragma unroll
    for (int q = 0; q < 2; q++) {
        float4 gi = *(const float4*)(gp + q * 4);
        float4 gf = *(const float4*)(gp + 512 + q * 4);
        float4 gg = *(const float4*)(gp + 1024 + q * 4);
        float4 go = *(const float4*)(gp + 1536 + q * 4);
        float4 co = *(const float4*)(cr + q * 4);
        float4 cv;
        __nv_bfloat16 bh4[4], bl4[4];
#pragma unroll
        for (int e = 0; e < 4; e++) {
            int lc = hb + q * 4 + e;
            float xi = gsm[row * 132 + lc]      + ((const float*)&gi)[e];
            float xf = gsm[row * 132 + 32 + lc] + ((const float*)&gf)[e];
            float xg = gsm[row * 132 + 64 + lc] + ((const float*)&gg)[e];
            float xo = gsm[row * 132 + 96 + lc] + ((const float*)&go)[e];
            float I = 1.f / (1.f + __expf(-xi));
            float F = 1.f / (1.f + __expf(-xf));
            float Gv = tanhf(xg);
            float O = 1.f / (1.f + __expf(-xo));
            float cn = F * ((const float*)&co)[e] + I * Gv;
            float hn = O * tanhf(cn);
            ((float*)&cv)[e] = cn;
            bh4[e] = __float2bfloat16(hn);
            bl4[e] = __float2bfloat16(hn - __bfloat162float(bh4[e]));
        }
        *(float4*)(cp + q * 4) = cv;
        __nv_bfloat162 p0; p0.x = bh4[0]; p0.y = bh4[1];
        __nv_bfloat162 p1; p1.x = bh4[2]; p1.y = bh4[3];
        __nv_bfloat162 q0; q0.x = bl4[0]; q0.y = bl4[1];
        __nv_bfloat162 q1; q1.x = bl4[2]; q1.y = bl4[3];
        *(__nv_bfloat162*)(hhp + q * 4)     = p0;
        *(__nv_bfloat162*)(hhp + q * 4 + 2) = p1;
        *(__nv_bfloat162*)(hlp + q * 4)     = q0;
        *(__nv_bfloat162*)(hlp + q * 4 + 2) = q1;
    }
}

// ---------------- head kernels -------------------------------------------------
__global__ void clstm_gather_r(const __nv_bfloat16* __restrict__ Hhi,
                               const __nv_bfloat16* __restrict__ Hlo,
                               float* __restrict__ r) {
    int b = blockIdx.x, i = blockIdx.y, h = threadIdx.x;
    size_t idx = ((size_t)(T_LEN - 1) * R_ROWS + i * B_SZ + b) * H_DIM + h;
    r[(size_t)b * 1536 + i * H_DIM + h] =
        __bfloat162float(Hhi[idx]) + __bfloat162float(Hlo[idx]);
}

__global__ void clstm_bn(float* __restrict__ x, const float* __restrict__ gamma,
                         const float* __restrict__ beta, int N) {
    __shared__ float s1[256], s2[256];
    int col = blockIdx.x;
    float v = x[(size_t)threadIdx.x * N + col];
    s1[threadIdx.x] = v; s2[threadIdx.x] = v * v;
    __syncthreads();
    for (int s = 128; s > 0; s >>= 1) {
        if (threadIdx.x < s) {
            s1[threadIdx.x] += s1[threadIdx.x + s];
            s2[threadIdx.x] += s2[threadIdx.x + s];
        }
        __syncthreads();
    }
    float m = s1[0] * (1.f / 256.f);
    float var = s2[0] * (1.f / 256.f) - m * m;
    float inv = rsqrtf(var + 1e-3f);
    x[(size_t)threadIdx.x * N + col] = gamma[col] * (v - m) * inv + beta[col];
}

__global__ void clstm_gemm_head(const float* __restrict__ A, const float* __restrict__ W,
                                const float* __restrict__ bias, float* __restrict__ C,
                                int K, int N, int act) {
    int n = blockIdx.x * 128 + threadIdx.x;
    int m0 = blockIdx.y * 16;
    if (n >= N) return;
    float s[16];
#pragma unroll
    for (int mm = 0; mm < 16; mm++) s[mm] = bias[n];
    for (int k = 0; k < K; k++) {
        float w = W[(size_t)k * N + n];
#pragma unroll
        for (int mm = 0; mm < 16; mm++)
            s[mm] += A[(size_t)(m0 + mm) * K + k] * w;
    }
    const float alpha = 1.6732632423543772f, scale = 1.0507009873554805f;
#pragma unroll
    for (int mm = 0; mm < 16; mm++) {
        float v = s[mm];
        if (act) v = scale * (v > 0.f ? v : alpha * expm1f(v));
        C[(size_t)(m0 + mm) * N + n] = v;
    }
}

// ---------------- launch --------------------------------------------------------
extern "C" void kernel_launch(void* const* d_in, const int* in_sizes, int n_in,
                              void* d_out, int out_size) {
    const int* t1 = (const int*)d_in[0];
    const int* t2 = (const int*)d_in[1];
    const int* t3 = (const int*)d_in[2];
    const float* emb = (const float*)d_in[3];
    const float* Wx = (const float*)d_in[4];
    const float* Wh = (const float*)d_in[5];
    const float* bb = (const float*)d_in[6];
    const float* g1 = (const float*)d_in[7];
    const float* be1 = (const float*)d_in[8];
    const float* W1 = (const float*)d_in[9];
    const float* bd1 = (const float*)d_in[10];
    const float* g2 = (const float*)d_in[11];
    const float* be2 = (const float*)d_in[12];
    const float* W2 = (const float*)d_in[13];
    const float* bd2 = (const float*)d_in[14];
    const float* g3 = (const float*)d_in[15];
    const float* be3 = (const float*)d_in[16];
    const float* W3 = (const float*)d_in[17];
    const float* bd3 = (const float*)d_in[18];
    float* out = (float*)d_out;

    float *G, *TAB, *C, *R, *H1, *H2;
    int* TOK;
    __nv_bfloat16 *Eh, *El, *WhPh, *WhPl, *WxTh, *WxTl, *sAh, *sAl, *sBh, *sBl;
    cudaGetSymbolAddress((void**)&G, d_Gbuf);
    cudaGetSymbolAddress((void**)&TAB, d_tab);
    cudaGetSymbolAddress((void**)&C, d_cst);
    cudaGetSymbolAddress((void**)&R, d_rbuf);
    cudaGetSymbolAddress((void**)&H1, d_h1buf);
    cudaGetSymbolAddress((void**)&H2, d_h2buf);
    cudaGetSymbolAddress((void**)&TOK, d_toks);
    cudaGetSymbolAddress((void**)&Eh, d_Ehi);
    cudaGetSymbolAddress((void**)&El, d_Elo);
    cudaGetSymbolAddress((void**)&WhPh, d_WhPhi);
    cudaGetSymbolAddress((void**)&WhPl, d_WhPlo);
    cudaGetSymbolAddress((void**)&WxTh, d_WxThi);
    cudaGetSymbolAddress((void**)&WxTl, d_WxTlo);
    cudaGetSymbolAddress((void**)&sAh, d_sAhi);
    cudaGetSymbolAddress((void**)&sAl, d_sAlo);
    cudaGetSymbolAddress((void**)&sBh, d_sBhi);
    cudaGetSymbolAddress((void**)&sBl, d_sBlo);

    cudaFuncSetAttribute(clstm_gemm_mma, cudaFuncAttributeMaxDynamicSharedMemorySize,
                         MMA_SMEM);
    cudaFuncSetAttribute(clstm_step_mma, cudaFuncAttributeMaxDynamicSharedMemorySize,
                         MMA_SMEM);

    // preprocessing
    cudaMemcpyAsync(TOK,          t1, 65536 * sizeof(int), cudaMemcpyDeviceToDevice, 0);
    cudaMemcpyAsync(TOK + 65536,  t2, 65536 * sizeof(int), cudaMemcpyDeviceToDevice, 0);
    cudaMemcpyAsync(TOK + 131072, t3, 65536 * sizeof(int), cudaMemcpyDeviceToDevice, 0);
    clstm_splitemb<<<V_SZ, 128>>>(emb, Eh, El);
    clstm_makeWsplit<<<dim3(64, 16, 3), dim3(32, 8)>>>(Wh, WhPh, WhPl, 1);
    clstm_makeWsplit<<<dim3(64, 16, 3), dim3(32, 8)>>>(Wx, WxTh, WxTl, 0);
    // vocab gate table: tab = emb @ Wx0 + b0   [32000, 2048]
    clstm_gemm_mma<<<dim3(16, V_SZ / 64), 256, MMA_SMEM>>>(
        Eh, El, WxTh, WxTl, bb, TAB);

    // layer 1: steps gather gates from tab[token]; output h seq -> sB
    cudaMemsetAsync(C, 0, (size_t)RH * sizeof(float), 0);
    for (int t = 0; t < T_LEN; t++) {
        clstm_step_mma<<<dim3(16, 12), 256, MMA_SMEM>>>(
            (const float*)0, TOK, TAB, t,
            sBh + (size_t)(t > 0 ? t - 1 : 0) * RH,
            sBl + (size_t)(t > 0 ? t - 1 : 0) * RH,
            WhPh, WhPl, C,
            sBh + (size_t)t * RH, sBl + (size_t)t * RH, t == 0 ? 1 : 0);
    }

    // layers 2,3
    __nv_bfloat16 *inH = sBh, *inL = sBl, *outH = sAh, *outL = sAl;
    for (int l = 1; l < 3; l++) {
        size_t woff = (size_t)l * G_COLS * H_DIM;
        clstm_gemm_mma<<<dim3(16, M_ALL / 64), 256, MMA_SMEM>>>(
            inH, inL, WxTh + woff, WxTl + woff, bb + (size_t)l * G_COLS, G);
        cudaMemsetAsync(C, 0, (size_t)RH * sizeof(float), 0);
        for (int t = 0; t < T_LEN; t++) {
            clstm_step_mma<<<dim3(16, 12), 256, MMA_SMEM>>>(
                G + (size_t)t * R_ROWS * G_COLS, (const int*)0, (const float*)0, 0,
                outH + (size_t)(t > 0 ? t - 1 : 0) * RH,
                outL + (size_t)(t > 0 ? t - 1 : 0) * RH,
                WhPh + woff, WhPl + woff, C,
                outH + (size_t)t * RH, outL + (size_t)t * RH, t == 0 ? 1 : 0);
        }
        __nv_bfloat16* tm;
        tm = inH; inH = outH; outH = tm;
        tm = inL; inL = outL; outL = tm;
    }

    // head
    clstm_gather_r<<<dim3(B_SZ, 3), H_DIM>>>(inH, inL, R);
    clstm_bn<<<1536, 256>>>(R, g1, be1, 1536);
    clstm_gemm_head<<<dim3(8, 16), 128>>>(R, W1, bd1, H1, 1536, 1024, 1);
    clstm_bn<<<1024, 256>>>(H1, g2, be2, 1024);
    clstm_gemm_head<<<dim3(1, 16), 128>>>(H1, W2, bd2, H2, 1024, H5, 1);
    clstm_bn<<<H5, 256>>>(H2, g3, be3, H5);
    clstm_gemm_head<<<dim3(1, 16), 128>>>(H2, W3, bd3, out, H5, 4, 0);
}

// round 8
// speedup vs baseline: 2.7166x; 1.1286x over previous
#include <cuda_runtime.h>
#include <cuda_bf16.h>
#include <math.h>
#include <stdint.h>
#include <stddef.h>

#define T_LEN 256
#define B_SZ  256
#define H_DIM 512
#define R_ROWS 768
#define G_COLS 2048
#define M_ALL  196608
#define V_SZ   32000
#define H5 102
#define RH 393216            // R_ROWS * H_DIM

// ---------------- static device scratch --------------------------------------
__device__ float d_Gbuf[402653184];   // [T][768][2048] h@Wx + b (layers 2,3)
__device__ float d_tab[65536000];     // [32000][2048] emb@Wx0 + b0
__device__ float d_cst[393216];
__device__ float d_rbuf[393216];
__device__ float d_h1buf[262144];
__device__ float d_h2buf[26112];
__device__ int   d_toks[196608];      // [3][256][256]
__device__ __nv_bfloat16 d_Ehi[16384000];           // emb split [32000][512]
__device__ __nv_bfloat16 d_Elo[16384000];
__device__ __nv_bfloat16 d_WhPhi[3 * 2048 * 512];   // Wh permuted [n'][k] hi
__device__ __nv_bfloat16 d_WhPlo[3 * 2048 * 512];
__device__ __nv_bfloat16 d_WxThi[3 * 2048 * 512];   // Wx transposed [n][k] hi
__device__ __nv_bfloat16 d_WxTlo[3 * 2048 * 512];
__device__ __nv_bfloat16 d_sAhi[100663296];         // h seq splits (ping)
__device__ __nv_bfloat16 d_sAlo[100663296];
__device__ __nv_bfloat16 d_sBhi[100663296];         // (pong)
__device__ __nv_bfloat16 d_sBlo[100663296];

// ---------------- helpers ------------------------------------------------------
__device__ __forceinline__ uint32_t smem_to_u32(const void* p) {
    uint32_t a;
    asm("{ .reg .u64 t; cvta.to.shared.u64 t, %1; cvt.u32.u64 %0, t; }"
        : "=r"(a) : "l"(p));
    return a;
}
__device__ __forceinline__ void ldmx4(uint32_t* r, uint32_t addr) {
    asm volatile("ldmatrix.sync.aligned.m8n8.x4.shared.b16 {%0,%1,%2,%3}, [%4];"
                 : "=r"(r[0]), "=r"(r[1]), "=r"(r[2]), "=r"(r[3]) : "r"(addr));
}
__device__ __forceinline__ void mma_bf16(float* c, const uint32_t* a,
                                         uint32_t b0, uint32_t b1) {
    asm volatile(
        "mma.sync.aligned.m16n8k16.row.col.f32.bf16.bf16.f32 "
        "{%0,%1,%2,%3}, {%4,%5,%6,%7}, {%8,%9}, {%0,%1,%2,%3};"
        : "+f"(c[0]), "+f"(c[1]), "+f"(c[2]), "+f"(c[3])
        : "r"(a[0]), "r"(a[1]), "r"(a[2]), "r"(a[3]), "r"(b0), "r"(b1));
}
#define CP_ASYNC16(dst, src) \
    asm volatile("cp.async.cg.shared.global [%0], [%1], 16;" :: "r"(dst), "l"(src))
#define CP_COMMIT()  asm volatile("cp.async.commit_group;" ::: "memory")
#define CP_WAIT0()   asm volatile("cp.async.wait_group 0;" ::: "memory")
#define CP_WAIT1()   asm volatile("cp.async.wait_group 1;" ::: "memory")

// ---- 64-row kernel smem (vocab table GEMM) ----
#define STAGE_B 55296
#define MMA_SMEM 110592
// ---- 96-row kernel smem ----
#define S96_AP 13824          // 96*144
#define S96_BP 18432          // 128*144
#define S96_STAGE 64512       // 2*AP + 2*BP
#define S96_SMEM 129024

// ---------------- emb -> bf16 split ---------------------------------------------
__global__ void clstm_splitemb(const float* __restrict__ emb,
                               __nv_bfloat16* __restrict__ Ehi,
                               __nv_bfloat16* __restrict__ Elo) {
    size_t base = (size_t)blockIdx.x * H_DIM + threadIdx.x * 4;
    float4 v = *(const float4*)(emb + base);
    float vv[4] = { v.x, v.y, v.z, v.w };
#pragma unroll
    for (int e = 0; e < 4; e++) {
        __nv_bfloat16 h = __float2bfloat16(vv[e]);
        Ehi[base + e] = h;
        Elo[base + e] = __float2bfloat16(vv[e] - __bfloat162float(h));
    }
}

// ---------------- W [k][n] -> [n'][k] bf16 split (optional gate permute) --------
__global__ void clstm_makeWsplit(const float* __restrict__ W,
                                 __nv_bfloat16* __restrict__ Phi,
                                 __nv_bfloat16* __restrict__ Plo, int permute) {
    __shared__ float tile[32][33];
    int n0 = blockIdx.x * 32, k0 = blockIdx.y * 32, l = blockIdx.z;
    const float* Wl = W + (size_t)l * H_DIM * G_COLS;
    int tx = threadIdx.x, ty = threadIdx.y;
#pragma unroll
    for (int it = 0; it < 4; it++)
        tile[ty + it * 8][tx] = Wl[(size_t)(k0 + ty + it * 8) * G_COLS + n0 + tx];
    __syncthreads();
    int s = n0 >> 9, cbb = (n0 >> 5) & 15;
    int np0 = permute ? (cbb * 128 + s * 32) : n0;
    __nv_bfloat16* ph = Phi + (size_t)l * G_COLS * H_DIM;
    __nv_bfloat16* pl = Plo + (size_t)l * G_COLS * H_DIM;
#pragma unroll
    for (int it = 0; it < 4; it++) {
        int nn = ty + it * 8;
        float v = tile[tx][nn];
        __nv_bfloat16 hi = __float2bfloat16(v);
        __nv_bfloat16 lo = __float2bfloat16(v - __bfloat162float(hi));
        ph[(size_t)(np0 + nn) * H_DIM + k0 + tx] = hi;
        pl[(size_t)(np0 + nn) * H_DIM + k0 + tx] = lo;
    }
}

// ---------------- HMMA 64-row GEMM (vocab table only) ---------------------------
__global__ void __launch_bounds__(256, 2)
clstm_gemm_mma(const __nv_bfloat16* __restrict__ Ahi, const __nv_bfloat16* __restrict__ Alo,
               const __nv_bfloat16* __restrict__ Bhi, const __nv_bfloat16* __restrict__ Blo,
               const float* __restrict__ bias, float* __restrict__ G) {
    extern __shared__ char smem[];
    const uint32_t sb = smem_to_u32(smem);
    const int tid = threadIdx.x, lane = tid & 31, w = tid >> 5;
    const int cb = blockIdx.x;
    const size_t bm = (size_t)blockIdx.y * 64;
    const __nv_bfloat16* asrc[2] = { Ahi + bm * H_DIM, Alo + bm * H_DIM };
    const __nv_bfloat16* bsrc[2] = { Bhi + (size_t)(cb * 128) * H_DIM,
                                     Blo + (size_t)(cb * 128) * H_DIM };
    const int lr = tid >> 3, lq = tid & 7;

    auto load_chunk = [&](int c, int s) {
        uint32_t stg = sb + (uint32_t)s * STAGE_B;
#pragma unroll
        for (int p = 0; p < 2; p++) {
            const __nv_bfloat16* gb = asrc[p] + c * 64;
            uint32_t sd = stg + p * 9216;
#pragma unroll
            for (int i = 0; i < 2; i++) {
                int r = lr + i * 32;
                CP_ASYNC16(sd + r * 144 + lq * 16,
                           (const void*)(gb + (size_t)r * H_DIM + lq * 8));
            }
        }
#pragma unroll
        for (int p = 0; p < 2; p++) {
            const __nv_bfloat16* gb = bsrc[p] + c * 64;
            uint32_t sd = stg + 18432 + p * 18432;
#pragma unroll
            for (int i = 0; i < 4; i++) {
                int r = lr + i * 32;
                CP_ASYNC16(sd + r * 144 + lq * 16,
                           (const void*)(gb + (size_t)r * H_DIM + lq * 8));
            }
        }
        CP_COMMIT();
    };

    const int m0 = (w >> 1) * 16, n0 = (w & 1) * 64;
    const int arow = (lane & 7) + ((lane & 8) ? 8 : 0);
    const int akq  = (lane & 16) ? 16 : 0;
    const int brow = (lane & 7) + ((lane & 16) ? 8 : 0);
    const int bkq  = (lane & 8) ? 16 : 0;

    float acc[8][4];
#pragma unroll
    for (int nt = 0; nt < 8; nt++)
#pragma unroll
        for (int e = 0; e < 4; e++) acc[nt][e] = 0.f;

    load_chunk(0, 0);
    for (int c = 0; c < 8; c++) {
        if (c < 7) { load_chunk(c + 1, (c + 1) & 1); CP_WAIT1(); }
        else       { CP_WAIT0(); }
        __syncthreads();
        uint32_t stg = sb + (uint32_t)(c & 1) * STAGE_B;
        uint32_t aH = stg, aL = stg + 9216, bH = stg + 18432, bL = stg + 36864;
#pragma unroll
        for (int ks = 0; ks < 4; ks++) {
            int kb = ks * 32;
            uint32_t ah[4], al[4], bh[4][4], bl[4][4];
            ldmx4(ah, aH + (m0 + arow) * 144 + kb + akq);
            ldmx4(al, aL + (m0 + arow) * 144 + kb + akq);
#pragma unroll
            for (int p = 0; p < 4; p++) {
                ldmx4(bh[p], bH + (n0 + p * 16 + brow) * 144 + kb + bkq);
                ldmx4(bl[p], bL + (n0 + p * 16 + brow) * 144 + kb + bkq);
            }
#pragma unroll
            for (int nt = 0; nt < 8; nt++)
                mma_bf16(acc[nt], ah, bh[nt >> 1][(nt & 1) * 2], bh[nt >> 1][(nt & 1) * 2 + 1]);
#pragma unroll
            for (int nt = 0; nt < 8; nt++)
                mma_bf16(acc[nt], ah, bl[nt >> 1][(nt & 1) * 2], bl[nt >> 1][(nt & 1) * 2 + 1]);
#pragma unroll
            for (int nt = 0; nt < 8; nt++)
                mma_bf16(acc[nt], al, bh[nt >> 1][(nt & 1) * 2], bh[nt >> 1][(nt & 1) * 2 + 1]);
        }
        __syncthreads();
    }

    float* gsm = (float*)smem;     // [64][132]
#pragma unroll
    for (int nt = 0; nt < 8; nt++) {
        int row = m0 + (lane >> 2);
        int col = n0 + nt * 8 + (lane & 3) * 2;
        gsm[row * 132 + col]     = acc[nt][0];
        gsm[row * 132 + col + 1] = acc[nt][1];
        gsm[(row + 8) * 132 + col]     = acc[nt][2];
        gsm[(row + 8) * 132 + col + 1] = acc[nt][3];
    }
    __syncthreads();

    int row = tid >> 2, c0 = (tid & 3) * 32;
    float* gp = G + (bm + row) * G_COLS + cb * 128;
#pragma unroll
    for (int q = 0; q < 8; q++) {
        int col = c0 + q * 4;
        float4 v = *(float4*)(gsm + row * 132 + col);
        float4 bv = *(const float4*)(bias + cb * 128 + col);
        v.x += bv.x; v.y += bv.y; v.z += bv.z; v.w += bv.w;
        *(float4*)(gp + col) = v;
    }
}

// =================== 96-row mainloop (shared by GEMM & step) ====================
// CTA tile 96 x 128, 384 threads = 12 warps (3 m-groups x 4 n-groups, 32x32).
// acc[2][4][4] per thread. K chunks of 64, 2-stage cp.async.
#define MAINLOOP96(ACC, ASRC, BSRC)                                              \
    const int lr_ = 0; (void)lr_;                                                \
    auto load96 = [&](int c, int s) {                                            \
        uint32_t stg = sb + (uint32_t)s * S96_STAGE;                             \
        _Pragma("unroll")                                                        \
        for (int i = 0; i < 10; i++) {                                           \
            int idx = tid + i * 384;                                             \
            if (idx < 3584) {                                                    \
                uint32_t d; const __nv_bfloat16* g;                              \
                if (idx < 1536) {                                                \
                    int p = idx >= 768, rem = idx - p * 768;                     \
                    int r = rem >> 3, q = rem & 7;                               \
                    d = stg + p * S96_AP + r * 144 + q * 16;                     \
                    g = ASRC[p] + c * 64 + (size_t)r * H_DIM + q * 8;            \
                } else {                                                         \
                    int j = idx - 1536;                                          \
                    int p = j >= 1024, rem = j - p * 1024;                       \
                    int r = rem >> 3, q = rem & 7;                               \
                    d = stg + 2 * S96_AP + p * S96_BP + r * 144 + q * 16;        \
                    g = BSRC[p] + c * 64 + (size_t)r * H_DIM + q * 8;            \
                }                                                                \
                CP_ASYNC16(d, (const void*)g);                                   \
            }                                                                    \
        }                                                                        \
        CP_COMMIT();                                                             \
    };                                                                           \
    load96(0, 0);                                                                \
    for (int c = 0; c < 8; c++) {                                                \
        if (c < 7) { load96(c + 1, (c + 1) & 1); CP_WAIT1(); }                   \
        else       { CP_WAIT0(); }                                               \
        __syncthreads();                                                         \
        uint32_t stg = sb + (uint32_t)(c & 1) * S96_STAGE;                       \
        uint32_t aH = stg, aL = stg + S96_AP;                                    \
        uint32_t bH = stg + 2 * S96_AP, bL = bH + S96_BP;                        \
        _Pragma("unroll")                                                        \
        for (int ks = 0; ks < 4; ks++) {                                         \
            int kb = ks * 32;                                                    \
            uint32_t ah[2][4], al[2][4], bh[2][4], bl[2][4];                     \
            _Pragma("unroll")                                                    \
            for (int mt = 0; mt < 2; mt++) {                                     \
                ldmx4(ah[mt], aH + (m0 + mt * 16 + arow) * 144 + kb + akq);      \
                ldmx4(al[mt], aL + (m0 + mt * 16 + arow) * 144 + kb + akq);      \
            }                                                                    \
            _Pragma("unroll")                                                    \
            for (int p = 0; p < 2; p++) {                                        \
                ldmx4(bh[p], bH + (n0 + p * 16 + brow) * 144 + kb + bkq);        \
                ldmx4(bl[p], bL + (n0 + p * 16 + brow) * 144 + kb + bkq);        \
            }                                                                    \
            _Pragma("unroll")                                                    \
            for (int mt = 0; mt < 2; mt++)                                       \
                _Pragma("unroll")                                                \
                for (int nt = 0; nt < 4; nt++)                                   \
                    mma_bf16(ACC[mt][nt], ah[mt],                                \
                             bh[nt >> 1][(nt & 1) * 2], bh[nt >> 1][(nt & 1) * 2 + 1]); \
            _Pragma("unroll")                                                    \
            for (int mt = 0; mt < 2; mt++)                                       \
                _Pragma("unroll")                                                \
                for (int nt = 0; nt < 4; nt++)                                   \
                    mma_bf16(ACC[mt][nt], ah[mt],                                \
                             bl[nt >> 1][(nt & 1) * 2], bl[nt >> 1][(nt & 1) * 2 + 1]); \
            _Pragma("unroll")                                                    \
            for (int mt = 0; mt < 2; mt++)                                       \
                _Pragma("unroll")                                                \
                for (int nt = 0; nt < 4; nt++)                                   \
                    mma_bf16(ACC[mt][nt], al[mt],                                \
                             bh[nt >> 1][(nt & 1) * 2], bh[nt >> 1][(nt & 1) * 2 + 1]); \
        }                                                                        \
        __syncthreads();                                                         \
    }

#define STASH96(ACC)                                                             \
    float* gsm = (float*)smem;                                                   \
    _Pragma("unroll")                                                            \
    for (int mt = 0; mt < 2; mt++)                                               \
        _Pragma("unroll")                                                        \
        for (int nt = 0; nt < 4; nt++) {                                         \
            int row = m0 + mt * 16 + (lane >> 2);                                \
            int col = n0 + nt * 8 + (lane & 3) * 2;                              \
            gsm[row * 132 + col]     = ACC[mt][nt][0];                           \
            gsm[row * 132 + col + 1] = ACC[mt][nt][1];                           \
            gsm[(row + 8) * 132 + col]     = ACC[mt][nt][2];                     \
            gsm[(row + 8) * 132 + col + 1] = ACC[mt][nt][3];                     \
        }                                                                        \
    __syncthreads();

// ---------------- 96-row batched GEMM (gate precompute, layers 2-3) -------------
__global__ void __launch_bounds__(384, 1)
clstm_gemm96(const __nv_bfloat16* __restrict__ Ahi, const __nv_bfloat16* __restrict__ Alo,
             const __nv_bfloat16* __restrict__ Bhi, const __nv_bfloat16* __restrict__ Blo,
             const float* __restrict__ bias, float* __restrict__ G) {
    extern __shared__ char smem[];
    const uint32_t sb = smem_to_u32(smem);
    const int tid = threadIdx.x, lane = tid & 31, w = tid >> 5;
    const int cb = blockIdx.x;
    const size_t bm = (size_t)blockIdx.y * 96;
    const __nv_bfloat16* asrc[2] = { Ahi + bm * H_DIM, Alo + bm * H_DIM };
    const __nv_bfloat16* bsrc[2] = { Bhi + (size_t)(cb * 128) * H_DIM,
                                     Blo + (size_t)(cb * 128) * H_DIM };
    const int m0 = (w >> 2) * 32, n0 = (w & 3) * 32;
    const int arow = (lane & 7) + ((lane & 8) ? 8 : 0);
    const int akq  = (lane & 16) ? 16 : 0;
    const int brow = (lane & 7) + ((lane & 16) ? 8 : 0);
    const int bkq  = (lane & 8) ? 16 : 0;

    float acc[2][4][4];
#pragma unroll
    for (int mt = 0; mt < 2; mt++)
#pragma unroll
        for (int nt = 0; nt < 4; nt++)
#pragma unroll
            for (int e = 0; e < 4; e++) acc[mt][nt][e] = 0.f;

    MAINLOOP96(acc, asrc, bsrc)
    STASH96(acc)

    int row = tid >> 2, c0 = (tid & 3) * 32;
    float* gp = G + (bm + row) * G_COLS + cb * 128;
#pragma unroll
    for (int q = 0; q < 8; q++) {
        int col = c0 + q * 4;
        float4 v = *(float4*)(gsm + row * 132 + col);
        float4 bv = *(const float4*)(bias + cb * 128 + col);
        v.x += bv.x; v.y += bv.y; v.z += bv.z; v.w += bv.w;
        *(float4*)(gp + col) = v;
    }
}

// ---------------- 96-row recurrent step (one wave: 128 CTAs) --------------------
__global__ void __launch_bounds__(384, 1)
clstm_step96(const float* __restrict__ Gt,
             const int* __restrict__ toks, const float* __restrict__ tab, int tstep,
             const __nv_bfloat16* __restrict__ Ahi, const __nv_bfloat16* __restrict__ Alo,
             const __nv_bfloat16* __restrict__ Bhi, const __nv_bfloat16* __restrict__ Blo,
             float* __restrict__ cst,
             __nv_bfloat16* __restrict__ Hhi, __nv_bfloat16* __restrict__ Hlo,
             int t0) {
    extern __shared__ char smem[];
    const uint32_t sb = smem_to_u32(smem);
    const int tid = threadIdx.x, lane = tid & 31, w = tid >> 5;
    const int cb = blockIdx.x;
    const size_t bm = (size_t)blockIdx.y * 96;
    const __nv_bfloat16* asrc[2] = { Ahi + bm * H_DIM, Alo + bm * H_DIM };
    const __nv_bfloat16* bsrc[2] = { Bhi + (size_t)(cb * 128) * H_DIM,
                                     Blo + (size_t)(cb * 128) * H_DIM };
    const int m0 = (w >> 2) * 32, n0 = (w & 3) * 32;
    const int arow = (lane & 7) + ((lane & 8) ? 8 : 0);
    const int akq  = (lane & 16) ? 16 : 0;
    const int brow = (lane & 7) + ((lane & 16) ? 8 : 0);
    const int bkq  = (lane & 8) ? 16 : 0;

    float acc[2][4][4];
#pragma unroll
    for (int mt = 0; mt < 2; mt++)
#pragma unroll
        for (int nt = 0; nt < 4; nt++)
#pragma unroll
            for (int e = 0; e < 4; e++) acc[mt][nt][e] = 0.f;

    if (!t0) {
        MAINLOOP96(acc, asrc, bsrc)
    }
    STASH96(acc)

    // fused LSTM epilogue: 96 rows x 32 h-cols, 8 per thread
    const int row = tid >> 2, hb = (tid & 3) * 8;
    const size_t grow = bm + row;
    const int hc0 = cb * 32 + hb;
    const float* gp;
    if (toks) {
        int tk = __ldg(toks + (((int)grow >> 8) << 16) + (((int)grow & 255) << 8) + tstep);
        gp = tab + (size_t)tk * G_COLS + hc0;
    } else {
        gp = Gt + grow * G_COLS + hc0;
    }
    const float* cr = cst + grow * H_DIM + hc0;
    float* cp = cst + grow * H_DIM + hc0;
    __nv_bfloat16* hhp = Hhi + grow * H_DIM + hc0;
    __nv_bfloat16* hlp = Hlo + grow * H_DIM + hc0;
#pragma unroll
    for (int q = 0; q < 2; q++) {
        float4 gi = *(const float4*)(gp + q * 4);
        float4 gf = *(const float4*)(gp + 512 + q * 4);
        float4 gg = *(const float4*)(gp + 1024 + q * 4);
        float4 go = *(const float4*)(gp + 1536 + q * 4);
        float4 co = *(const float4*)(cr + q * 4);
        float4 cv;
        __nv_bfloat16 bh4[4], bl4[4];
#pragma unroll
        for (int e = 0; e < 4; e++) {
            int lc = hb + q * 4 + e;
            float xi = gsm[row * 132 + lc]      + ((const float*)&gi)[e];
            float xf = gsm[row * 132 + 32 + lc] + ((const float*)&gf)[e];
            float xg = gsm[row * 132 + 64 + lc] + ((const float*)&gg)[e];
            float xo = gsm[row * 132 + 96 + lc] + ((const float*)&go)[e];
            float I = 1.f / (1.f + __expf(-xi));
            float F = 1.f / (1.f + __expf(-xf));
            float Gv = tanhf(xg);
            float O = 1.f / (1.f + __expf(-xo));
            float cn = F * ((const float*)&co)[e] + I * Gv;
            float hn = O * tanhf(cn);
            ((float*)&cv)[e] = cn;
            bh4[e] = __float2bfloat16(hn);
            bl4[e] = __float2bfloat16(hn - __bfloat162float(bh4[e]));
        }
        *(float4*)(cp + q * 4) = cv;
        __nv_bfloat162 p0; p0.x = bh4[0]; p0.y = bh4[1];
        __nv_bfloat162 p1; p1.x = bh4[2]; p1.y = bh4[3];
        __nv_bfloat162 q0; q0.x = bl4[0]; q0.y = bl4[1];
        __nv_bfloat162 q1; q1.x = bl4[2]; q1.y = bl4[3];
        *(__nv_bfloat162*)(hhp + q * 4)     = p0;
        *(__nv_bfloat162*)(hhp + q * 4 + 2) = p1;
        *(__nv_bfloat162*)(hlp + q * 4)     = q0;
        *(__nv_bfloat162*)(hlp + q * 4 + 2) = q1;
    }
}

// ---------------- head kernels -------------------------------------------------
__global__ void clstm_gather_r(const __nv_bfloat16* __restrict__ Hhi,
                               const __nv_bfloat16* __restrict__ Hlo,
                               float* __restrict__ r) {
    int b = blockIdx.x, i = blockIdx.y, h = threadIdx.x;
    size_t idx = ((size_t)(T_LEN - 1) * R_ROWS + i * B_SZ + b) * H_DIM + h;
    r[(size_t)b * 1536 + i * H_DIM + h] =
        __bfloat162float(Hhi[idx]) + __bfloat162float(Hlo[idx]);
}

__global__ void clstm_bn(float* __restrict__ x, const float* __restrict__ gamma,
                         const float* __restrict__ beta, int N) {
    __shared__ float s1[256], s2[256];
    int col = blockIdx.x;
    float v = x[(size_t)threadIdx.x * N + col];
    s1[threadIdx.x] = v; s2[threadIdx.x] = v * v;
    __syncthreads();
    for (int s = 128; s > 0; s >>= 1) {
        if (threadIdx.x < s) {
            s1[threadIdx.x] += s1[threadIdx.x + s];
            s2[threadIdx.x] += s2[threadIdx.x + s];
        }
        __syncthreads();
    }
    float m = s1[0] * (1.f / 256.f);
    float var = s2[0] * (1.f / 256.f) - m * m;
    float inv = rsqrtf(var + 1e-3f);
    x[(size_t)threadIdx.x * N + col] = gamma[col] * (v - m) * inv + beta[col];
}

__global__ void clstm_gemm_head(const float* __restrict__ A, const float* __restrict__ W,
                                const float* __restrict__ bias, float* __restrict__ C,
                                int K, int N, int act) {
    int n = blockIdx.x * 128 + threadIdx.x;
    int m0 = blockIdx.y * 16;
    if (n >= N) return;
    float s[16];
#pragma unroll
    for (int mm = 0; mm < 16; mm++) s[mm] = bias[n];
    for (int k = 0; k < K; k++) {
        float w = W[(size_t)k * N + n];
#pragma unroll
        for (int mm = 0; mm < 16; mm++)
            s[mm] += A[(size_t)(m0 + mm) * K + k] * w;
    }
    const float alpha = 1.6732632423543772f, scale = 1.0507009873554805f;
#pragma unroll
    for (int mm = 0; mm < 16; mm++) {
        float v = s[mm];
        if (act) v = scale * (v > 0.f ? v : alpha * expm1f(v));
        C[(size_t)(m0 + mm) * N + n] = v;
    }
}

// ---------------- launch --------------------------------------------------------
extern "C" void kernel_launch(void* const* d_in, const int* in_sizes, int n_in,
                              void* d_out, int out_size) {
    const int* t1 = (const int*)d_in[0];
    const int* t2 = (const int*)d_in[1];
    const int* t3 = (const int*)d_in[2];
    const float* emb = (const float*)d_in[3];
    const float* Wx = (const float*)d_in[4];
    const float* Wh = (const float*)d_in[5];
    const float* bb = (const float*)d_in[6];
    const float* g1 = (const float*)d_in[7];
    const float* be1 = (const float*)d_in[8];
    const float* W1 = (const float*)d_in[9];
    const float* bd1 = (const float*)d_in[10];
    const float* g2 = (const float*)d_in[11];
    const float* be2 = (const float*)d_in[12];
    const float* W2 = (const float*)d_in[13];
    const float* bd2 = (const float*)d_in[14];
    const float* g3 = (const float*)d_in[15];
    const float* be3 = (const float*)d_in[16];
    const float* W3 = (const float*)d_in[17];
    const float* bd3 = (const float*)d_in[18];
    float* out = (float*)d_out;

    float *G, *TAB, *C, *R, *H1, *H2;
    int* TOK;
    __nv_bfloat16 *Eh, *El, *WhPh, *WhPl, *WxTh, *WxTl, *sAh, *sAl, *sBh, *sBl;
    cudaGetSymbolAddress((void**)&G, d_Gbuf);
    cudaGetSymbolAddress((void**)&TAB, d_tab);
    cudaGetSymbolAddress((void**)&C, d_cst);
    cudaGetSymbolAddress((void**)&R, d_rbuf);
    cudaGetSymbolAddress((void**)&H1, d_h1buf);
    cudaGetSymbolAddress((void**)&H2, d_h2buf);
    cudaGetSymbolAddress((void**)&TOK, d_toks);
    cudaGetSymbolAddress((void**)&Eh, d_Ehi);
    cudaGetSymbolAddress((void**)&El, d_Elo);
    cudaGetSymbolAddress((void**)&WhPh, d_WhPhi);
    cudaGetSymbolAddress((void**)&WhPl, d_WhPlo);
    cudaGetSymbolAddress((void**)&WxTh, d_WxThi);
    cudaGetSymbolAddress((void**)&WxTl, d_WxTlo);
    cudaGetSymbolAddress((void**)&sAh, d_sAhi);
    cudaGetSymbolAddress((void**)&sAl, d_sAlo);
    cudaGetSymbolAddress((void**)&sBh, d_sBhi);
    cudaGetSymbolAddress((void**)&sBl, d_sBlo);

    cudaFuncSetAttribute(clstm_gemm_mma, cudaFuncAttributeMaxDynamicSharedMemorySize,
                         MMA_SMEM);
    cudaFuncSetAttribute(clstm_gemm96, cudaFuncAttributeMaxDynamicSharedMemorySize,
                         S96_SMEM);
    cudaFuncSetAttribute(clstm_step96, cudaFuncAttributeMaxDynamicSharedMemorySize,
                         S96_SMEM);

    // preprocessing
    cudaMemcpyAsync(TOK,          t1, 65536 * sizeof(int), cudaMemcpyDeviceToDevice, 0);
    cudaMemcpyAsync(TOK + 65536,  t2, 65536 * sizeof(int), cudaMemcpyDeviceToDevice, 0);
    cudaMemcpyAsync(TOK + 131072, t3, 65536 * sizeof(int), cudaMemcpyDeviceToDevice, 0);
    clstm_splitemb<<<V_SZ, 128>>>(emb, Eh, El);
    clstm_makeWsplit<<<dim3(64, 16, 3), dim3(32, 8)>>>(Wh, WhPh, WhPl, 1);
    clstm_makeWsplit<<<dim3(64, 16, 3), dim3(32, 8)>>>(Wx, WxTh, WxTl, 0);
    // vocab gate table: tab = emb @ Wx0 + b0   [32000, 2048]
    clstm_gemm_mma<<<dim3(16, V_SZ / 64), 256, MMA_SMEM>>>(
        Eh, El, WxTh, WxTl, bb, TAB);

    // layer 1: steps gather gates from tab[token]; output h seq -> sB
    cudaMemsetAsync(C, 0, (size_t)RH * sizeof(float), 0);
    for (int t = 0; t < T_LEN; t++) {
        clstm_step96<<<dim3(16, 8), 384, S96_SMEM>>>(
            (const float*)0, TOK, TAB, t,
            sBh + (size_t)(t > 0 ? t - 1 : 0) * RH,
            sBl + (size_t)(t > 0 ? t - 1 : 0) * RH,
            WhPh, WhPl, C,
            sBh + (size_t)t * RH, sBl + (size_t)t * RH, t == 0 ? 1 : 0);
    }

    // layers 2,3
    __nv_bfloat16 *inH = sBh, *inL = sBl, *outH = sAh, *outL = sAl;
    for (int l = 1; l < 3; l++) {
        size_t woff = (size_t)l * G_COLS * H_DIM;
        clstm_gemm96<<<dim3(16, M_ALL / 96), 384, S96_SMEM>>>(
            inH, inL, WxTh + woff, WxTl + woff, bb + (size_t)l * G_COLS, G);
        cudaMemsetAsync(C, 0, (size_t)RH * sizeof(float), 0);
        for (int t = 0; t < T_LEN; t++) {
            clstm_step96<<<dim3(16, 8), 384, S96_SMEM>>>(
                G + (size_t)t * R_ROWS * G_COLS, (const int*)0, (const float*)0, 0,
                outH + (size_t)(t > 0 ? t - 1 : 0) * RH,
                outL + (size_t)(t > 0 ? t - 1 : 0) * RH,
                WhPh + woff, WhPl + woff, C,
                outH + (size_t)t * RH, outL + (size_t)t * RH, t == 0 ? 1 : 0);
        }
        __nv_bfloat16* tm;
        tm = inH; inH = outH; outH = tm;
        tm = inL; inL = outL; outL = tm;
    }

    // head
    clstm_gather_r<<<dim3(B_SZ, 3), H_DIM>>>(inH, inL, R);
    clstm_bn<<<1536, 256>>>(R, g1, be1, 1536);
    clstm_gemm_head<<<dim3(8, 16), 128>>>(R, W1, bd1, H1, 1536, 1024, 1);
    clstm_bn<<<1024, 256>>>(H1, g2, be2, 1024);
    clstm_gemm_head<<<dim3(1, 16), 128>>>(H1, W2, bd2, H2, 1024, H5, 1);
    clstm_bn<<<H5, 256>>>(H2, g3, be3, H5);
    clstm_gemm_head<<<dim3(1, 16), 128>>>(H2, W3, bd3, out, H5, 4, 0);
}